// round 13
// baseline (speedup 1.0000x reference)
#include <cuda_runtime.h>
#include <cstdint>

#define N_QUBITS 16
#define DIM 65536
#define BATCH 128

// Scratch state buffers (device globals: allocation-free rule).
__device__ __align__(16) float4 g_state0[BATCH * DIM / 2];
__device__ __align__(16) float4 g_state1[BATCH * DIM / 2];
__device__ float g_partial[BATCH * 16 * 16];   // [b][loGroup][q]

// Precomputed per-(batch,layer) gate data (filled in k_init's prep phase).
__device__ float2 g_cs  [BATCH * 4 * 16];          // rotation (c,s) per bit p
__device__ __align__(16) float2 g_TLt [BATCH * 4 * 2 * 256];   // TL[b8][lo]
__device__ __align__(16) float2 g_THt [BATCH * 4 * 256 * 2];   // TH[hi][b0]

// ---------------------------------------------------------------------------
__device__ __forceinline__ float2 cmul(float2 a, float2 b) {
    return make_float2(a.x * b.x - a.y * b.y, a.x * b.y + a.y * b.x);
}
__device__ __forceinline__ float2 sel(float2 v, int bit) {
    return bit ? make_float2(v.x, -v.y) : v;
}
// real rotation on complex pair
__device__ __forceinline__ void rot2(float2& A, float2& B, float c, float s) {
    float2 a = A, b = B;
    A = make_float2(c * a.x - s * b.x, c * a.y - s * b.y);
    B = make_float2(s * a.x + c * b.x, s * a.y + c * b.y);
}

// CNOT-ring permutation sigma (GF(2)-linear).
__device__ __forceinline__ int sigma16(int i) {
    int t = i;
    t ^= t >> 1; t ^= t >> 2; t ^= t >> 4; t ^= t >> 8;
    int b15 = (t ^ (i >> 15)) & 1;
    return (t & 0x7FFF) | (b15 << 15);
}

// ---------------------------------------------------------------------------
// First column of G = Rot(phi,theta,omega) @ RY(x).
__device__ void gate_col(const float* __restrict__ x,
                         const float* __restrict__ w,
                         int b, int l, int q,
                         float& g0, float& g1, float& g4, float& g5) {
    float xv  = x[(b * 4 + l) * 16 + q];
    const float* wp = w + (l * 16 + q) * 3;
    float phi = wp[0], th = wp[1], om = wp[2];
    float ct, st, cr, sr, sp, cp, sm, cm;
    sincosf(0.5f * th, &st, &ct);
    sincosf(0.5f * xv, &sr, &cr);
    sincosf(0.5f * (phi + om), &sp, &cp);
    sincosf(0.5f * (phi - om), &sm, &cm);
    float m00r =  cp * ct, m00i = -sp * ct;
    float m01r = -cm * st, m01i = -sm * st;
    float m10r =  cm * st, m10i = -sm * st;
    float m11r =  cp * ct, m11i =  sp * ct;
    g0 = m00r * cr + m01r * sr;  g1 = m00i * cr + m01i * sr;
    g4 = m10r * cr + m11r * sr;  g5 = m10i * cr + m11i * sr;
}

__device__ void gate_decomp(const float* __restrict__ x,
                            const float* __restrict__ w,
                            int b, int l, int q,
                            float2& cs, float2& q0, float2& p0) {
    float g0, g1, g4, g5;
    gate_col(x, w, b, l, q, g0, g1, g4, g5);
    float ca = sqrtf(g0 * g0 + g1 * g1);
    float sb = sqrtf(g4 * g4 + g5 * g5);
    float au = atan2f(g1, g0);
    float av = atan2f(g5, g4);
    float s1, c1, s2, c2;
    sincosf(0.5f * (au + av), &s1, &c1);
    sincosf(0.5f * (au - av), &s2, &c2);
    cs = make_float2(ca, sb);
    q0 = make_float2(c1, s1);
    p0 = make_float2(c2, s2);
}

// ---------------------------------------------------------------------------
// K1 (merged prep + init) — R9 proven version.
__global__ __launch_bounds__(256)
void k_init(const float* __restrict__ x, const float* __restrict__ w,
            float4* __restrict__ st4) {
    int b = blockIdx.x, tid = threadIdx.x;

    __shared__ float2 sq0[3][16], sp0[3][16], sid[16];
    if (tid < 48) {
        int l = tid >> 4, p = tid & 15;
        float2 cs, q0, p0;
        gate_decomp(x, w, b, l + 1, 15 - p, cs, q0, p0);
        sq0[l][p] = q0; sp0[l][p] = p0;
        g_cs[(b * 4 + l + 1) * 16 + p] = cs;
    }
    if (tid < 16) sid[tid] = make_float2(1.f, 0.f);
    __syncthreads();

    #pragma unroll
    for (int li = 0; li < 3; li++) {
        const float2* q2 = sq0[li];
        const float2* p1 = (li == 0) ? sid : sp0[li - 1];
        int base = (b * 4 + li + 1);
        {
            int m = tid;
            float2 acc = sel(q2[0], m & 1);
            #pragma unroll
            for (int p = 1; p <= 7; p++) acc = cmul(acc, sel(q2[p], (m >> p) & 1));
            #pragma unroll
            for (int p = 0; p <= 6; p++)
                acc = cmul(acc, sel(p1[p], ((m >> p) ^ (m >> (p + 1))) & 1));
            int m7 = (m >> 7) & 1;
            g_TLt[(base * 2 + 0) * 256 + m] = cmul(acc, sel(p1[7], m7));
            g_TLt[(base * 2 + 1) * 256 + m] = cmul(acc, sel(p1[7], m7 ^ 1));
        }
        {
            int hi = tid;
            float2 acc = sel(q2[8], hi & 1);
            #pragma unroll
            for (int p = 9; p <= 15; p++)
                acc = cmul(acc, sel(q2[p], (hi >> (p - 8)) & 1));
            #pragma unroll
            for (int p = 8; p <= 13; p++)
                acc = cmul(acc, sel(p1[p], ((hi >> (p - 8)) ^ (hi >> (p - 7))) & 1));
            int h6 = (hi >> 6) & 1, h7 = (hi >> 7) & 1;
            #pragma unroll
            for (int b0 = 0; b0 < 2; b0++) {
                float2 a2 = cmul(acc, sel(p1[14], h6 ^ b0 ^ h7));
                a2 = cmul(a2, sel(p1[15], b0 ^ h7));
                g_THt[(base * 256 + hi) * 2 + b0] = a2;
            }
        }
    }

    __shared__ float2 colA[16][2];
    __shared__ __align__(16) float2 AL[2][256];
    __shared__ float2 AH[2][256];
    if (tid < 16) {
        float g0, g1, g4, g5;
        gate_col(x, w, b, 0, 15 - tid, g0, g1, g4, g5);
        colA[tid][0] = make_float2(g0, g1);
        colA[tid][1] = make_float2(g4, g5);
    }
    __syncthreads();
    {
        int m = tid;
        float2 acc = colA[0][(m ^ (m >> 1)) & 1];
        #pragma unroll
        for (int p = 1; p <= 6; p++)
            acc = cmul(acc, colA[p][((m >> p) ^ (m >> (p + 1))) & 1]);
        int m7 = (m >> 7) & 1;
        AL[0][m] = cmul(acc, colA[7][m7]);
        AL[1][m] = cmul(acc, colA[7][m7 ^ 1]);
    }
    {
        int m = tid;
        float2 acc = colA[8][(m ^ (m >> 1)) & 1];
        #pragma unroll
        for (int p = 9; p <= 13; p++)
            acc = cmul(acc, colA[p][((m >> (p - 8)) ^ (m >> (p - 7))) & 1]);
        int h6 = (m >> 6) & 1, h7 = (m >> 7) & 1;
        AH[0][m] = cmul(acc, cmul(colA[14][h6 ^ h7],     colA[15][h7]));
        AH[1][m] = cmul(acc, cmul(colA[14][h6 ^ 1 ^ h7], colA[15][1 ^ h7]));
    }
    __syncthreads();
    float4* base = st4 + (size_t)b * (DIM / 2);
    #pragma unroll 4
    for (int it = 0; it < 128; it++) {
        int j0 = it * 512 + tid * 2;
        int lo = j0 & 255, hi = j0 >> 8;
        const float2* ALs = AL[hi & 1];
        float2 a0 = cmul(AH[0][hi], ALs[lo]);
        float2 a1 = cmul(AH[1][hi], ALs[lo + 1]);
        base[it * 256 + tid] = make_float4(a0.x, a0.y, a1.x, a1.y);
    }
}

// ---------------------------------------------------------------------------
// KA: combined diagonal + gates on lo bits 0..7. Proven R9 version, UNCHANGED.
// grid (32, BATCH), 256 threads.
__global__ __launch_bounds__(256)
void k_low(int layer, float4* __restrict__ st4) {
    int b = blockIdx.y, tid = threadIdx.x;
    int wid = tid >> 5, lane = tid & 31;
    __shared__ float2 gcs[8];
    __shared__ __align__(16) float2 TL[2][256];
    __shared__ float2 THs[8][2];

    int base = b * 4 + layer;
    if (tid < 8) gcs[tid] = g_cs[base * 16 + tid];
    TL[0][tid] = g_TLt[(base * 2 + 0) * 256 + tid];
    TL[1][tid] = g_TLt[(base * 2 + 1) * 256 + tid];
    if (tid < 16) {
        int wi = tid >> 1, b0 = tid & 1;
        int hig = blockIdx.x * 8 + wi;
        THs[wi][b0] = g_THt[(base * 256 + hig) * 2 + b0];
    }
    __syncthreads();

    int hi = blockIdx.x * 8 + wid;
    float2 TH0 = THs[wid][0], TH1 = THs[wid][1];
    const float4* TL4 = reinterpret_cast<const float4*>(TL[hi & 1]);
    float4* sbase = st4 + (size_t)b * (DIM / 2) + hi * 128;
    float4 v[4];
    #pragma unroll
    for (int r = 0; r < 4; r++) v[r] = sbase[r * 32 + lane];
    #pragma unroll
    for (int r = 0; r < 4; r++) {
        float4 dd = TL4[r * 32 + lane];
        float2 d0 = cmul(TH0, make_float2(dd.x, dd.y));
        float2 d1 = cmul(TH1, make_float2(dd.z, dd.w));
        float2 A = cmul(make_float2(v[r].x, v[r].y), d0);
        float2 B = cmul(make_float2(v[r].z, v[r].w), d1);
        v[r] = make_float4(A.x, A.y, B.x, B.y);
    }
    {
        float c = gcs[0].x, s = gcs[0].y;
        #pragma unroll
        for (int r = 0; r < 4; r++) {
            float4 a = v[r];
            v[r] = make_float4(c * a.x - s * a.z, c * a.y - s * a.w,
                               s * a.x + c * a.z, s * a.y + c * a.w);
        }
    }
    #pragma unroll
    for (int p = 1; p <= 5; p++) {
        float2 cp = gcs[p];
        float c = cp.x;
        float s = ((lane >> (p - 1)) & 1) ? cp.y : -cp.y;
        int msk = 1 << (p - 1);
        #pragma unroll
        for (int r = 0; r < 4; r++) {
            float px = __shfl_xor_sync(0xffffffffu, v[r].x, msk);
            float py = __shfl_xor_sync(0xffffffffu, v[r].y, msk);
            float pz = __shfl_xor_sync(0xffffffffu, v[r].z, msk);
            float pw = __shfl_xor_sync(0xffffffffu, v[r].w, msk);
            v[r].x = c * v[r].x + s * px;
            v[r].y = c * v[r].y + s * py;
            v[r].z = c * v[r].z + s * pz;
            v[r].w = c * v[r].w + s * pw;
        }
    }
    #pragma unroll
    for (int pb = 0; pb < 2; pb++) {
        int m = 1 << pb;
        float2 cp = gcs[6 + pb];
        float c = cp.x, s = cp.y;
        #pragma unroll
        for (int r = 0; r < 4; r++)
            if (!(r & m)) {
                float4 A = v[r], B = v[r + m];
                v[r]     = make_float4(c * A.x - s * B.x, c * A.y - s * B.y,
                                       c * A.z - s * B.z, c * A.w - s * B.w);
                v[r + m] = make_float4(s * A.x + c * B.x, s * A.y + c * B.y,
                                       s * A.z + c * B.z, s * A.w + c * B.w);
            }
    }
    #pragma unroll
    for (int r = 0; r < 4; r++) sbase[r * 32 + lane] = v[r];
}

// ---------------------------------------------------------------------------
// KB: gates on hi bits 0..7, zero-shuffle 3-phase register butterflies.
// 512 threads, grid (16, BATCH).
// Non-final: NEW fully-coalesced scatter — phase-C results go back to the
// tile, then outputs are re-partitioned by j (lane nibble = j0..j3 so each
// 16-lane group writes one contiguous 128B run; i = sigma^{-1}(j) addresses
// the tile via 3 XORs). Halves STG sector traffic vs the old parity-split
// scatter. FINAL: unchanged signed-marginal readout.
template <bool FINAL>
__global__ __launch_bounds__(512)
void k_high(int layer, const float2* __restrict__ in,
            float2* __restrict__ outst, float* __restrict__ part) {
    __shared__ float2 tile[16 * 257];                     // 32.9 KB
    int b = blockIdx.y, logrp = blockIdx.x, tid = threadIdx.x;
    int base = b * 4 + layer;
    int lo4 = tid & 15, s = tid >> 4;                     // s: 0..31
    float2 u[8];

    // ---- phase A: hi bits 0..2 ----
    {
        const float2* gb = in + (size_t)b * DIM + (s << 3) * 256 + logrp * 16 + lo4;
        #pragma unroll
        for (int k = 0; k < 8; k++) u[k] = gb[k * 256];
        #pragma unroll
        for (int p = 0; p < 3; p++) {
            float2 cp = g_cs[base * 16 + 8 + p];
            int m = 1 << p;
            #pragma unroll
            for (int k = 0; k < 8; k++)
                if (!(k & m)) rot2(u[k], u[k + m], cp.x, cp.y);
        }
        #pragma unroll
        for (int k = 0; k < 8; k++)
            tile[lo4 * 257 + (s << 3) + k] = u[k];
    }
    __syncthreads();

    // ---- phase B: hi bits 3..5 ----
    {
        int c = s & 7, d = s >> 3;
        int hbase = (d << 6) | c;
        #pragma unroll
        for (int m = 0; m < 8; m++) u[m] = tile[lo4 * 257 + hbase + (m << 3)];
        #pragma unroll
        for (int p = 0; p < 3; p++) {
            float2 cp = g_cs[base * 16 + 11 + p];
            int mm = 1 << p;
            #pragma unroll
            for (int m = 0; m < 8; m++)
                if (!(m & mm)) rot2(u[m], u[m + mm], cp.x, cp.y);
        }
        #pragma unroll
        for (int m = 0; m < 8; m++) tile[lo4 * 257 + hbase + (m << 3)] = u[m];
    }
    __syncthreads();

    // ---- phase C: hi bits 6..7 (regs n: bit0 = hi bit 0, bits1..2 = hi 6..7) ----
    {
        int hbase = s << 1;
        #pragma unroll
        for (int n = 0; n < 8; n++)
            u[n] = tile[lo4 * 257 + hbase + ((n >> 1) << 6) + (n & 1)];
        #pragma unroll
        for (int p = 0; p < 2; p++) {
            float2 cp = g_cs[base * 16 + 14 + p];
            int mm = 2 << p;
            #pragma unroll
            for (int n = 0; n < 8; n++)
                if (!(n & mm)) rot2(u[n], u[n + mm], cp.x, cp.y);
        }
    }

    if (!FINAL) {
        // write phase-C results back to the tile (same addresses as the
        // phase-C reads: conflict-free), then re-partition by output index j.
        #pragma unroll
        for (int n = 0; n < 8; n++)
            tile[lo4 * 257 + (s << 1) + ((n >> 1) << 6) + (n & 1)] = u[n];
        __syncthreads();

        // j parameterization: lane nibble jn = j0..j3; t5 = {j4, j9..j12};
        // iter n = {j13, j14, j15}. j5..j8 follow from logrp prefix-XORs.
        int jn = tid & 15;
        int t5 = tid >> 4;
        int j4 = t5 & 1;
        int j9_12 = t5 >> 1;
        int g = logrp;
        int G1 = g & 1;
        int G2 = G1 ^ ((g >> 1) & 1);
        int G3 = G2 ^ ((g >> 2) & 1);
        int G4 = G3 ^ ((g >> 3) & 1);
        int jmid = ((G1 << 5) | (G2 << 6) | (G3 << 7) | (G4 << 8)) ^ (j4 ? 0x1E0 : 0);
        int jbase = jn | (j4 << 4) | jmid | (j9_12 << 9);
        // sigma^{-1}: i bits 0..3 and 8..15 from j
        int lo4r  = (jn ^ (jn >> 1)) ^ (j4 << 3);
        int hbR   = (G4 ^ j4) | (j9_12 << 1);        // h = j8..j15 (low 5 bits)
        int hmask = (jn & 1) ? 0xC0 : 0;             // j0 flips i14, i15
        float2* ob = outst + (size_t)b * DIM;
        #pragma unroll
        for (int n = 0; n < 8; n++) {
            int h = hbR | (n << 5);
            int hir = (h ^ (h >> 1)) ^ hmask;
            ob[jbase | (n << 13)] = tile[lo4r * 257 + hir];
        }
    } else {
        __syncthreads();
        float* pf = (float*)tile;
        #pragma unroll
        for (int n = 0; n < 8; n++) {
            int hi = ((n >> 1) << 6) | (s << 1) | (n & 1);
            pf[lo4 * 257 + hi] = u[n].x * u[n].x + u[n].y * u[n].y;
        }
        __syncthreads();

        int wid = tid >> 5, lane = tid & 31;
        float spv[8], smv[8];
        if (tid < 256) {
            #pragma unroll
            for (int r = 0; r < 8; r++) {
                float p0 = pf[(wid * 2)     * 257 + r * 32 + lane];
                float p1 = pf[(wid * 2 + 1) * 257 + r * 32 + lane];
                spv[r] = p0 + p1; smv[r] = p0 - p1;
            }
        }
        __syncthreads();
        float* S  = pf;
        float* S2 = pf + 4096;
        if (tid < 256) {
            #pragma unroll
            for (int r = 0; r < 8; r++) {
                S[wid * 256 + r * 32 + lane]        = spv[r];
                S[2048 + wid * 256 + r * 32 + lane] = smv[r];
            }
        }
        __syncthreads();

        if (tid < 256) {
            float V0 = 0.f, V1 = 0.f, V2 = 0.f, V3 = 0.f, V4 = 0.f;
            #pragma unroll
            for (int w2 = 0; w2 < 8; w2++) {
                float sp = S[w2 * 256 + tid];
                float sm = S[2048 + w2 * 256 + tid];
                int pw  = __popc(w2) & 1;
                int pw2 = __popc(w2 >> 1) & 1;
                int pw3 = (w2 >> 2) & 1;
                V4 += sp;
                V1 += pw  ? -sp : sp;
                V2 += pw2 ? -sp : sp;
                V3 += pw3 ? -sp : sp;
                V0 += pw  ? -sm : sm;
            }
            float A[12];
            int t = tid;
            int pfb = __popc(t) & 1;
            #pragma unroll
            for (int k = 0; k < 7; k++)
                A[k] = (__popc(t >> k) & 1) ? -V4 : V4;
            A[7]  = pfb ? -V0 : V0;
            A[8]  = pfb ? -V1 : V1;
            A[9]  = pfb ? -V2 : V2;
            A[10] = pfb ? -V3 : V3;
            A[11] = (__popc(t & 0x7F) & 1) ? -V0 : V0;
            #pragma unroll
            for (int k = 0; k < 12; k++) {
                float a = A[k];
                #pragma unroll
                for (int o = 16; o; o >>= 1) a += __shfl_down_sync(0xffffffffu, a, o);
                if (lane == 0) S2[wid * 12 + k] = a;
            }
        }
        __syncthreads();
        if (tid < 12) {
            float sum = 0.f;
            #pragma unroll
            for (int w2 = 0; w2 < 8; w2++) sum += S2[w2 * 12 + tid];
            S2[96 + tid] = sum;
        }
        __syncthreads();
        if (tid < 16) {
            const float* R = S2 + 96;
            int q = tid, lg = logrp;
            float sgnAll = (__popc(lg) & 1) ? -1.f : 1.f;
            float val;
            if (q == 0)        val = sgnAll * R[11];
            else if (q < 8)    val = R[7 - q];
            else if (q < 12) {
                int P = 15 - q;
                val = ((__popc(lg >> (P - 4)) & 1) ? -1.f : 1.f) * R[0];
            } else {
                int P = 15 - q;
                val = sgnAll * R[7 + P];
            }
            part[(b * 16 + lg) * 16 + q] = val;
        }
    }
}

// Final deterministic reduction of partials -> out[b][q]
__global__ __launch_bounds__(256)
void k_reduce(const float* __restrict__ part, float* __restrict__ out) {
    int idx = blockIdx.x * 256 + threadIdx.x;
    int b = idx >> 4, q = idx & 15;
    float s = 0.f;
    #pragma unroll
    for (int gp = 0; gp < 16; gp++) s += part[(b * 16 + gp) * 16 + q];
    out[idx] = s;
}

// ---------------------------------------------------------------------------
extern "C" void kernel_launch(void* const* d_in, const int* in_sizes, int n_in,
                              void* d_out, int out_size) {
    const float* x = (const float*)d_in[0];
    const float* w = (const float*)d_in[1];
    if (n_in >= 2 && in_sizes[0] == 192) { const float* t = x; x = w; w = t; }
    float* out = (float*)d_out;

    float4 *s0, *s1; float* part;
    cudaGetSymbolAddress((void**)&s0, g_state0);
    cudaGetSymbolAddress((void**)&s1, g_state1);
    cudaGetSymbolAddress((void**)&part, g_partial);

    k_init<<<BATCH, 256>>>(x, w, s0);

    k_low <<<dim3(32, BATCH), 256>>>(1, s0);
    k_high<false><<<dim3(16, BATCH), 512>>>(1, (const float2*)s0, (float2*)s1, nullptr);

    k_low <<<dim3(32, BATCH), 256>>>(2, s1);
    k_high<false><<<dim3(16, BATCH), 512>>>(2, (const float2*)s1, (float2*)s0, nullptr);

    k_low <<<dim3(32, BATCH), 256>>>(3, s0);
    k_high<true> <<<dim3(16, BATCH), 512>>>(3, (const float2*)s0, nullptr, part);

    k_reduce<<<8, 256>>>(part, out);
}

// round 14
// speedup vs baseline: 1.0771x; 1.0771x over previous
#include <cuda_runtime.h>
#include <cstdint>

#define N_QUBITS 16
#define DIM 65536
#define BATCH 128

// Scratch state buffers (device globals: allocation-free rule).
__device__ __align__(16) float4 g_state0[BATCH * DIM / 2];
__device__ __align__(16) float4 g_state1[BATCH * DIM / 2];
__device__ float g_partial[BATCH * 16 * 16];   // [b][loGroup][q]

// Precomputed per-(batch,layer) gate data (filled in k_init's prep phase).
__device__ float2 g_cs  [BATCH * 4 * 16];          // rotation (c,s) per bit p
__device__ __align__(16) float2 g_TLt [BATCH * 4 * 2 * 256];   // TL[b8][lo]  (flat 512/layer)
__device__ __align__(16) float2 g_THt [BATCH * 4 * 256 * 2];   // TH[hi][b0]  (flat 512/layer)

// ---------------------------------------------------------------------------
__device__ __forceinline__ float2 cmul(float2 a, float2 b) {
    return make_float2(a.x * b.x - a.y * b.y, a.x * b.y + a.y * b.x);
}
__device__ __forceinline__ float2 sel(float2 v, int bit) {
    return bit ? make_float2(v.x, -v.y) : v;
}
// real rotation on complex pair
__device__ __forceinline__ void rot2(float2& A, float2& B, float c, float s) {
    float2 a = A, b = B;
    A = make_float2(c * a.x - s * b.x, c * a.y - s * b.y);
    B = make_float2(s * a.x + c * b.x, s * a.y + c * b.y);
}

// CNOT-ring permutation sigma (GF(2)-linear).
__device__ __forceinline__ int sigma16(int i) {
    int t = i;
    t ^= t >> 1; t ^= t >> 2; t ^= t >> 4; t ^= t >> 8;
    int b15 = (t ^ (i >> 15)) & 1;
    return (t & 0x7FFF) | (b15 << 15);
}

// ---------------------------------------------------------------------------
// First column of G = Rot(phi,theta,omega) @ RY(x).
__device__ void gate_col(const float* __restrict__ x,
                         const float* __restrict__ w,
                         int b, int l, int q,
                         float& g0, float& g1, float& g4, float& g5) {
    float xv  = x[(b * 4 + l) * 16 + q];
    const float* wp = w + (l * 16 + q) * 3;
    float phi = wp[0], th = wp[1], om = wp[2];
    float ct, st, cr, sr, sp, cp, sm, cm;
    sincosf(0.5f * th, &st, &ct);
    sincosf(0.5f * xv, &sr, &cr);
    sincosf(0.5f * (phi + om), &sp, &cp);
    sincosf(0.5f * (phi - om), &sm, &cm);
    float m00r =  cp * ct, m00i = -sp * ct;
    float m01r = -cm * st, m01i = -sm * st;
    float m10r =  cm * st, m10i = -sm * st;
    float m11r =  cp * ct, m11i =  sp * ct;
    g0 = m00r * cr + m01r * sr;  g1 = m00i * cr + m01i * sr;
    g4 = m10r * cr + m11r * sr;  g5 = m10i * cr + m11i * sr;
}

__device__ void gate_decomp(const float* __restrict__ x,
                            const float* __restrict__ w,
                            int b, int l, int q,
                            float2& cs, float2& q0, float2& p0) {
    float g0, g1, g4, g5;
    gate_col(x, w, b, l, q, g0, g1, g4, g5);
    float ca = sqrtf(g0 * g0 + g1 * g1);
    float sb = sqrtf(g4 * g4 + g5 * g5);
    float au = atan2f(g1, g0);
    float av = atan2f(g5, g4);
    float s1, c1, s2, c2;
    sincosf(0.5f * (au + av), &s1, &c1);
    sincosf(0.5f * (au - av), &s2, &c2);
    cs = make_float2(ca, sb);
    q0 = make_float2(c1, s1);
    p0 = make_float2(c2, s2);
}

// ---------------------------------------------------------------------------
// K1 (merged prep + init). Prep: decompositions + diagonal tables, layers 1..3.
// Init: layer-0 product state in the sigma-permuted domain, WITH the layer-1
// combined diagonal folded into the AL/AH tables (same index structure).
__global__ __launch_bounds__(256)
void k_init(const float* __restrict__ x, const float* __restrict__ w,
            float4* __restrict__ st4) {
    int b = blockIdx.x, tid = threadIdx.x;

    __shared__ float2 sq0[3][16], sp0[3][16], sid[16];
    if (tid < 48) {
        int l = tid >> 4, p = tid & 15;
        float2 cs, q0, p0;
        gate_decomp(x, w, b, l + 1, 15 - p, cs, q0, p0);
        sq0[l][p] = q0; sp0[l][p] = p0;
        g_cs[(b * 4 + l + 1) * 16 + p] = cs;
    }
    if (tid < 16) sid[tid] = make_float2(1.f, 0.f);
    __syncthreads();

    #pragma unroll
    for (int li = 0; li < 3; li++) {
        const float2* q2 = sq0[li];
        const float2* p1 = (li == 0) ? sid : sp0[li - 1];
        int base = (b * 4 + li + 1);
        {
            int m = tid;
            float2 acc = sel(q2[0], m & 1);
            #pragma unroll
            for (int p = 1; p <= 7; p++) acc = cmul(acc, sel(q2[p], (m >> p) & 1));
            #pragma unroll
            for (int p = 0; p <= 6; p++)
                acc = cmul(acc, sel(p1[p], ((m >> p) ^ (m >> (p + 1))) & 1));
            int m7 = (m >> 7) & 1;
            g_TLt[(base * 2 + 0) * 256 + m] = cmul(acc, sel(p1[7], m7));
            g_TLt[(base * 2 + 1) * 256 + m] = cmul(acc, sel(p1[7], m7 ^ 1));
        }
        {
            int hi = tid;
            float2 acc = sel(q2[8], hi & 1);
            #pragma unroll
            for (int p = 9; p <= 15; p++)
                acc = cmul(acc, sel(q2[p], (hi >> (p - 8)) & 1));
            #pragma unroll
            for (int p = 8; p <= 13; p++)
                acc = cmul(acc, sel(p1[p], ((hi >> (p - 8)) ^ (hi >> (p - 7))) & 1));
            int h6 = (hi >> 6) & 1, h7 = (hi >> 7) & 1;
            #pragma unroll
            for (int b0 = 0; b0 < 2; b0++) {
                float2 a2 = cmul(acc, sel(p1[14], h6 ^ b0 ^ h7));
                a2 = cmul(a2, sel(p1[15], b0 ^ h7));
                g_THt[(base * 256 + hi) * 2 + b0] = a2;
            }
        }
    }

    __shared__ float2 colA[16][2];
    __shared__ __align__(16) float2 AL[2][256];
    __shared__ float2 AH[2][256];
    if (tid < 16) {
        float g0, g1, g4, g5;
        gate_col(x, w, b, 0, 15 - tid, g0, g1, g4, g5);
        colA[tid][0] = make_float2(g0, g1);
        colA[tid][1] = make_float2(g4, g5);
    }
    __syncthreads();
    int base1 = b * 4 + 1;
    {
        int m = tid;
        float2 acc = colA[0][(m ^ (m >> 1)) & 1];
        #pragma unroll
        for (int p = 1; p <= 6; p++)
            acc = cmul(acc, colA[p][((m >> p) ^ (m >> (p + 1))) & 1]);
        int m7 = (m >> 7) & 1;
        // fold layer-1 diagonal lo-factor (same [b8][lo] structure)
        AL[0][m] = cmul(cmul(acc, colA[7][m7]),     g_TLt[(base1 * 2 + 0) * 256 + m]);
        AL[1][m] = cmul(cmul(acc, colA[7][m7 ^ 1]), g_TLt[(base1 * 2 + 1) * 256 + m]);
    }
    {
        int m = tid;
        float2 acc = colA[8][(m ^ (m >> 1)) & 1];
        #pragma unroll
        for (int p = 9; p <= 13; p++)
            acc = cmul(acc, colA[p][((m >> (p - 8)) ^ (m >> (p - 7))) & 1]);
        int h6 = (m >> 6) & 1, h7 = (m >> 7) & 1;
        // fold layer-1 diagonal hi-factor (same [b0][hi] structure)
        AH[0][m] = cmul(cmul(acc, cmul(colA[14][h6 ^ h7],     colA[15][h7])),
                        g_THt[(base1 * 256 + m) * 2 + 0]);
        AH[1][m] = cmul(cmul(acc, cmul(colA[14][h6 ^ 1 ^ h7], colA[15][1 ^ h7])),
                        g_THt[(base1 * 256 + m) * 2 + 1]);
    }
    __syncthreads();
    float4* base = st4 + (size_t)b * (DIM / 2);
    #pragma unroll 4
    for (int it = 0; it < 128; it++) {
        int j0 = it * 512 + tid * 2;
        int lo = j0 & 255, hi = j0 >> 8;
        const float2* ALs = AL[hi & 1];
        float2 a0 = cmul(AH[0][hi], ALs[lo]);
        float2 a1 = cmul(AH[1][hi], ALs[lo + 1]);
        base[it * 256 + tid] = make_float4(a0.x, a0.y, a1.x, a1.y);
    }
}

// ---------------------------------------------------------------------------
// KA: PURE gates on lo bits 0..7 (diagonal now applied upstream at the
// producer's scatter / init). R9 structure minus all diagonal work.
// grid (32, BATCH), 256 threads.
__global__ __launch_bounds__(256)
void k_low(int layer, float4* __restrict__ st4) {
    int b = blockIdx.y, tid = threadIdx.x;
    int wid = tid >> 5, lane = tid & 31;
    __shared__ float2 gcs[8];
    if (tid < 8) gcs[tid] = g_cs[(b * 4 + layer) * 16 + tid];
    __syncthreads();

    int hi = blockIdx.x * 8 + wid;
    float4* sbase = st4 + (size_t)b * (DIM / 2) + hi * 128;
    float4 v[4];
    #pragma unroll
    for (int r = 0; r < 4; r++) v[r] = sbase[r * 32 + lane];
    {   // bit0 gate (intra-float4)
        float c = gcs[0].x, s = gcs[0].y;
        #pragma unroll
        for (int r = 0; r < 4; r++) {
            float4 a = v[r];
            v[r] = make_float4(c * a.x - s * a.z, c * a.y - s * a.w,
                               s * a.x + c * a.z, s * a.y + c * a.w);
        }
    }
    #pragma unroll
    for (int p = 1; p <= 5; p++) {
        float2 cp = gcs[p];
        float c = cp.x;
        float s = ((lane >> (p - 1)) & 1) ? cp.y : -cp.y;
        int msk = 1 << (p - 1);
        #pragma unroll
        for (int r = 0; r < 4; r++) {
            float px = __shfl_xor_sync(0xffffffffu, v[r].x, msk);
            float py = __shfl_xor_sync(0xffffffffu, v[r].y, msk);
            float pz = __shfl_xor_sync(0xffffffffu, v[r].z, msk);
            float pw = __shfl_xor_sync(0xffffffffu, v[r].w, msk);
            v[r].x = c * v[r].x + s * px;
            v[r].y = c * v[r].y + s * py;
            v[r].z = c * v[r].z + s * pz;
            v[r].w = c * v[r].w + s * pw;
        }
    }
    #pragma unroll
    for (int pb = 0; pb < 2; pb++) {
        int m = 1 << pb;
        float2 cp = gcs[6 + pb];
        float c = cp.x, s = cp.y;
        #pragma unroll
        for (int r = 0; r < 4; r++)
            if (!(r & m)) {
                float4 A = v[r], B = v[r + m];
                v[r]     = make_float4(c * A.x - s * B.x, c * A.y - s * B.y,
                                       c * A.z - s * B.z, c * A.w - s * B.w);
                v[r + m] = make_float4(s * A.x + c * B.x, s * A.y + c * B.y,
                                       s * A.z + c * B.z, s * A.w + c * B.w);
            }
    }
    #pragma unroll
    for (int r = 0; r < 4; r++) sbase[r * 32 + lane] = v[r];
}

// ---------------------------------------------------------------------------
// KB: gates on hi bits 0..7, zero-shuffle 3-phase register butterflies (R9
// proven). Non-final NEW: applies the NEXT layer's combined diagonal Dc(j)
// at the scatter (smem-preloaded tables; latency-slack kernel absorbs it).
// FINAL: unchanged signed-marginal readout.
template <bool FINAL>
__global__ __launch_bounds__(512)
void k_high(int layer, const float2* __restrict__ in,
            float2* __restrict__ outst, float* __restrict__ part) {
    __shared__ float2 tile[16 * 257];                     // 32.9 KB
    __shared__ float2 dTL[512];                           // next-layer TL[b8][lo]
    __shared__ float2 dTH[512];                           // next-layer TH[hi][b0]
    int b = blockIdx.y, logrp = blockIdx.x, tid = threadIdx.x;
    int base = b * 4 + layer;
    int lo4 = tid & 15, s = tid >> 4;                     // s: 0..31
    float2 u[8];

    if (!FINAL) {                     // preload next-layer diagonal tables
        int nbase = base + 1;
        dTL[tid] = g_TLt[nbase * 512 + tid];
        dTH[tid] = g_THt[nbase * 512 + tid];
    }

    // ---- phase A: hi bits 0..2 ----
    {
        const float2* gb = in + (size_t)b * DIM + (s << 3) * 256 + logrp * 16 + lo4;
        #pragma unroll
        for (int k = 0; k < 8; k++) u[k] = gb[k * 256];
        #pragma unroll
        for (int p = 0; p < 3; p++) {
            float2 cp = g_cs[base * 16 + 8 + p];
            int m = 1 << p;
            #pragma unroll
            for (int k = 0; k < 8; k++)
                if (!(k & m)) rot2(u[k], u[k + m], cp.x, cp.y);
        }
        #pragma unroll
        for (int k = 0; k < 8; k++)
            tile[lo4 * 257 + (s << 3) + k] = u[k];
    }
    __syncthreads();

    // ---- phase B: hi bits 3..5 ----
    {
        int c = s & 7, d = s >> 3;
        int hbase = (d << 6) | c;
        #pragma unroll
        for (int m = 0; m < 8; m++) u[m] = tile[lo4 * 257 + hbase + (m << 3)];
        #pragma unroll
        for (int p = 0; p < 3; p++) {
            float2 cp = g_cs[base * 16 + 11 + p];
            int mm = 1 << p;
            #pragma unroll
            for (int m = 0; m < 8; m++)
                if (!(m & mm)) rot2(u[m], u[m + mm], cp.x, cp.y);
        }
        #pragma unroll
        for (int m = 0; m < 8; m++) tile[lo4 * 257 + hbase + (m << 3)] = u[m];
    }
    __syncthreads();

    // ---- phase C: hi bits 6..7 (regs n: bit0 = hi bit 0, bits1..2 = hi 6..7) ----
    {
        int hbase = s << 1;
        #pragma unroll
        for (int n = 0; n < 8; n++)
            u[n] = tile[lo4 * 257 + hbase + ((n >> 1) << 6) + (n & 1)];
        #pragma unroll
        for (int p = 0; p < 2; p++) {
            float2 cp = g_cs[base * 16 + 14 + p];
            int mm = 2 << p;
            #pragma unroll
            for (int n = 0; n < 8; n++)
                if (!(n & mm)) rot2(u[n], u[n + mm], cp.x, cp.y);
        }
    }

    if (!FINAL) {
        // scatter with next-layer diagonal: out[j] = u * TL[j8][jlo] * TH[jhi][j0]
        int jbase = sigma16((s << 9) | (logrp << 4) | lo4);
        float2* ob = outst + (size_t)b * DIM;
        #pragma unroll
        for (int n = 0; n < 8; n++) {
            int j = jbase ^ sigma16(((n & 1) << 8) | ((n >> 1) << 14));
            int jlo = j & 255, jhi = j >> 8;
            float2 d = cmul(dTL[((jhi & 1) << 8) | jlo], dTH[(jhi << 1) | (j & 1)]);
            ob[j] = cmul(u[n], d);
        }
    } else {
        __syncthreads();
        float* pf = (float*)tile;
        #pragma unroll
        for (int n = 0; n < 8; n++) {
            int hi = ((n >> 1) << 6) | (s << 1) | (n & 1);
            pf[lo4 * 257 + hi] = u[n].x * u[n].x + u[n].y * u[n].y;
        }
        __syncthreads();

        int wid = tid >> 5, lane = tid & 31;
        float spv[8], smv[8];
        if (tid < 256) {
            #pragma unroll
            for (int r = 0; r < 8; r++) {
                float p0 = pf[(wid * 2)     * 257 + r * 32 + lane];
                float p1 = pf[(wid * 2 + 1) * 257 + r * 32 + lane];
                spv[r] = p0 + p1; smv[r] = p0 - p1;
            }
        }
        __syncthreads();
        float* S  = pf;
        float* S2 = pf + 4096;
        if (tid < 256) {
            #pragma unroll
            for (int r = 0; r < 8; r++) {
                S[wid * 256 + r * 32 + lane]        = spv[r];
                S[2048 + wid * 256 + r * 32 + lane] = smv[r];
            }
        }
        __syncthreads();

        if (tid < 256) {
            float V0 = 0.f, V1 = 0.f, V2 = 0.f, V3 = 0.f, V4 = 0.f;
            #pragma unroll
            for (int w2 = 0; w2 < 8; w2++) {
                float sp = S[w2 * 256 + tid];
                float sm = S[2048 + w2 * 256 + tid];
                int pw  = __popc(w2) & 1;
                int pw2 = __popc(w2 >> 1) & 1;
                int pw3 = (w2 >> 2) & 1;
                V4 += sp;
                V1 += pw  ? -sp : sp;
                V2 += pw2 ? -sp : sp;
                V3 += pw3 ? -sp : sp;
                V0 += pw  ? -sm : sm;
            }
            float A[12];
            int t = tid;
            int pfb = __popc(t) & 1;
            #pragma unroll
            for (int k = 0; k < 7; k++)
                A[k] = (__popc(t >> k) & 1) ? -V4 : V4;
            A[7]  = pfb ? -V0 : V0;
            A[8]  = pfb ? -V1 : V1;
            A[9]  = pfb ? -V2 : V2;
            A[10] = pfb ? -V3 : V3;
            A[11] = (__popc(t & 0x7F) & 1) ? -V0 : V0;
            #pragma unroll
            for (int k = 0; k < 12; k++) {
                float a = A[k];
                #pragma unroll
                for (int o = 16; o; o >>= 1) a += __shfl_down_sync(0xffffffffu, a, o);
                if (lane == 0) S2[wid * 12 + k] = a;
            }
        }
        __syncthreads();
        if (tid < 12) {
            float sum = 0.f;
            #pragma unroll
            for (int w2 = 0; w2 < 8; w2++) sum += S2[w2 * 12 + tid];
            S2[96 + tid] = sum;
        }
        __syncthreads();
        if (tid < 16) {
            const float* R = S2 + 96;
            int q = tid, lg = logrp;
            float sgnAll = (__popc(lg) & 1) ? -1.f : 1.f;
            float val;
            if (q == 0)        val = sgnAll * R[11];
            else if (q < 8)    val = R[7 - q];
            else if (q < 12) {
                int P = 15 - q;
                val = ((__popc(lg >> (P - 4)) & 1) ? -1.f : 1.f) * R[0];
            } else {
                int P = 15 - q;
                val = sgnAll * R[7 + P];
            }
            part[(b * 16 + lg) * 16 + q] = val;
        }
    }
}

// Final deterministic reduction of partials -> out[b][q]
__global__ __launch_bounds__(256)
void k_reduce(const float* __restrict__ part, float* __restrict__ out) {
    int idx = blockIdx.x * 256 + threadIdx.x;
    int b = idx >> 4, q = idx & 15;
    float s = 0.f;
    #pragma unroll
    for (int gp = 0; gp < 16; gp++) s += part[(b * 16 + gp) * 16 + q];
    out[idx] = s;
}

// ---------------------------------------------------------------------------
extern "C" void kernel_launch(void* const* d_in, const int* in_sizes, int n_in,
                              void* d_out, int out_size) {
    const float* x = (const float*)d_in[0];
    const float* w = (const float*)d_in[1];
    if (n_in >= 2 && in_sizes[0] == 192) { const float* t = x; x = w; w = t; }
    float* out = (float*)d_out;

    float4 *s0, *s1; float* part;
    cudaGetSymbolAddress((void**)&s0, g_state0);
    cudaGetSymbolAddress((void**)&s1, g_state1);
    cudaGetSymbolAddress((void**)&part, g_partial);

    k_init<<<BATCH, 256>>>(x, w, s0);

    k_low <<<dim3(32, BATCH), 256>>>(1, s0);
    k_high<false><<<dim3(16, BATCH), 512>>>(1, (const float2*)s0, (float2*)s1, nullptr);

    k_low <<<dim3(32, BATCH), 256>>>(2, s1);
    k_high<false><<<dim3(16, BATCH), 512>>>(2, (const float2*)s1, (float2*)s0, nullptr);

    k_low <<<dim3(32, BATCH), 256>>>(3, s0);
    k_high<true> <<<dim3(16, BATCH), 512>>>(3, (const float2*)s0, nullptr, part);

    k_reduce<<<8, 256>>>(part, out);
}

// round 15
// speedup vs baseline: 1.3323x; 1.2369x over previous
#include <cuda_runtime.h>
#include <cstdint>

#define N_QUBITS 16
#define DIM 65536
#define BATCH 128

// Scratch state buffers (device globals: allocation-free rule).
__device__ __align__(16) float4 g_state0[BATCH * DIM / 2];
__device__ __align__(16) float4 g_state1[BATCH * DIM / 2];
__device__ float g_partial[BATCH * 16 * 16];   // [b][loGroup][q]

// Precomputed per-(batch,layer) gate data.
__device__ float2 g_cs  [BATCH * 4 * 16];          // rotation (c,s) per bit p (slots 2,3)
__device__ __align__(16) float2 g_TLt [BATCH * 4 * 2 * 256];   // TL[b8][lo] per slot
__device__ __align__(16) float2 g_THt [BATCH * 4 * 256 * 2];   // TH[hi][b0] per slot

// MPS bond-4 tables after layer-0 + sigma0 + full layer-1 gates (j-indexed).
__device__ __align__(16) float2 g_F4[BATCH * 4 * 256];
__device__ __align__(16) float2 g_G4[BATCH * 4 * 256];

// ---------------------------------------------------------------------------
__device__ __forceinline__ float2 cmul(float2 a, float2 b) {
    return make_float2(a.x * b.x - a.y * b.y, a.x * b.y + a.y * b.x);
}
__device__ __forceinline__ float2 sel(float2 v, int bit) {
    return bit ? make_float2(v.x, -v.y) : v;
}
__device__ __forceinline__ void rot2(float2& A, float2& B, float c, float s) {
    float2 a = A, b = B;
    A = make_float2(c * a.x - s * b.x, c * a.y - s * b.y);
    B = make_float2(s * a.x + c * b.x, s * a.y + c * b.y);
}

// CNOT-ring permutation sigma (GF(2)-linear).
__device__ __forceinline__ int sigma16(int i) {
    int t = i;
    t ^= t >> 1; t ^= t >> 2; t ^= t >> 4; t ^= t >> 8;
    int b15 = (t ^ (i >> 15)) & 1;
    return (t & 0x7FFF) | (b15 << 15);
}

// ---------------------------------------------------------------------------
// First column of G = Rot(phi,theta,omega) @ RY(x): G00=(g0,g1), G10=(g4,g5).
// SU(2): G01 = -conj(G10), G11 = conj(G00).
__device__ void gate_col(const float* __restrict__ x,
                         const float* __restrict__ w,
                         int b, int l, int q,
                         float& g0, float& g1, float& g4, float& g5) {
    float xv  = x[(b * 4 + l) * 16 + q];
    const float* wp = w + (l * 16 + q) * 3;
    float phi = wp[0], th = wp[1], om = wp[2];
    float ct, st, cr, sr, sp, cp, sm, cm;
    sincosf(0.5f * th, &st, &ct);
    sincosf(0.5f * xv, &sr, &cr);
    sincosf(0.5f * (phi + om), &sp, &cp);
    sincosf(0.5f * (phi - om), &sm, &cm);
    float m00r =  cp * ct, m00i = -sp * ct;
    float m01r = -cm * st, m01i = -sm * st;
    float m10r =  cm * st, m10i = -sm * st;
    float m11r =  cp * ct, m11i =  sp * ct;
    g0 = m00r * cr + m01r * sr;  g1 = m00i * cr + m01i * sr;
    g4 = m10r * cr + m11r * sr;  g5 = m10i * cr + m11i * sr;
}

__device__ void gate_decomp(const float* __restrict__ x,
                            const float* __restrict__ w,
                            int b, int l, int q,
                            float2& cs, float2& q0, float2& p0) {
    float g0, g1, g4, g5;
    gate_col(x, w, b, l, q, g0, g1, g4, g5);
    float ca = sqrtf(g0 * g0 + g1 * g1);
    float sb = sqrtf(g4 * g4 + g5 * g5);
    float au = atan2f(g1, g0);
    float av = atan2f(g5, g4);
    float s1, c1, s2, c2;
    sincosf(0.5f * (au + av), &s1, &c1);
    sincosf(0.5f * (au - av), &s2, &c2);
    cs = make_float2(ca, sb);
    q0 = make_float2(c1, s1);
    p0 = make_float2(c2, s2);
}

// ---------------------------------------------------------------------------
// K_TAB: grid (2, BATCH). Side 0 builds the lo-side (F) tables, side 1 the
// hi-side (G) tables. Each side: layer-0 column products with sigma0 index
// maps (validated k_init formulas) -> K=4 indicator tables -> full layer-1
// gates applied table-wise. Also writes layer-2/3 rotation coeffs and
// diagonal tables: slot 2 = pure q0(L2) (p1=id), slot 3 = q0(L3)*p0(L2)
// combined (R13 formulas).
__global__ __launch_bounds__(256)
void k_tab(const float* __restrict__ x, const float* __restrict__ w) {
    int b = blockIdx.y, side = blockIdx.x, tid = threadIdx.x;
    __shared__ float2 colA[8][2];      // layer-0 first columns (this side's bits)
    __shared__ float2 gl1[8][2];       // layer-1 full gates (G00, G10)
    __shared__ float2 q2[8], p2[8], q3[8];
    __shared__ float2 T[4][256];

    if (side == 0) {
        if (tid < 8) {
            float a0, a1, b0, b1;
            gate_col(x, w, b, 0, 15 - tid, a0, a1, b0, b1);
            colA[tid][0] = make_float2(a0, a1);
            colA[tid][1] = make_float2(b0, b1);
            gate_col(x, w, b, 1, 15 - tid, a0, a1, b0, b1);
            gl1[tid][0] = make_float2(a0, a1);
            gl1[tid][1] = make_float2(b0, b1);
        } else if (tid < 16) {
            int p = tid - 8;
            float2 cs, q0, p0;
            gate_decomp(x, w, b, 2, 15 - p, cs, q0, p0);
            g_cs[(b * 4 + 2) * 16 + p] = cs;
            q2[p] = q0; p2[p] = p0;
        } else if (tid < 24) {
            int p = tid - 16;
            float2 cs, q0, p0;
            gate_decomp(x, w, b, 3, 15 - p, cs, q0, p0);
            g_cs[(b * 4 + 3) * 16 + p] = cs;
            q3[p] = q0;
        }
    } else {
        if (tid < 8) {
            float a0, a1, b0, b1;
            gate_col(x, w, b, 0, 7 - tid, a0, a1, b0, b1);     // bit 8+tid
            colA[tid][0] = make_float2(a0, a1);
            colA[tid][1] = make_float2(b0, b1);
            gate_col(x, w, b, 1, 7 - tid, a0, a1, b0, b1);
            gl1[tid][0] = make_float2(a0, a1);
            gl1[tid][1] = make_float2(b0, b1);
        } else if (tid < 16) {
            int p = tid - 8;
            float2 cs, q0, p0;
            gate_decomp(x, w, b, 2, 7 - p, cs, q0, p0);
            g_cs[(b * 4 + 2) * 16 + 8 + p] = cs;
            q2[p] = q0; p2[p] = p0;
        } else if (tid < 24) {
            int p = tid - 16;
            float2 cs, q0, p0;
            gate_decomp(x, w, b, 3, 7 - p, cs, q0, p0);
            g_cs[(b * 4 + 3) * 16 + 8 + p] = cs;
            q3[p] = q0;
        }
    }
    __syncthreads();

    // ---- build K=4 indicator tables (j-indexed, sigma0 map inside) ----
    {
        int m = tid;
        float2 z = make_float2(0.f, 0.f);
        if (side == 0) {
            float2 acc = colA[0][(m ^ (m >> 1)) & 1];
            #pragma unroll
            for (int p = 1; p <= 6; p++)
                acc = cmul(acc, colA[p][((m >> p) ^ (m >> (p + 1))) & 1]);
            int m7 = (m >> 7) & 1;
            float2 AL0 = cmul(acc, colA[7][m7]);
            float2 AL1 = cmul(acc, colA[7][m7 ^ 1]);
            int a = m & 1;                       // indicator [j0 = a]
            T[a * 2 + 0][m] = AL0;  T[a * 2 + 1][m] = AL1;
            T[(a ^ 1) * 2 + 0][m] = z;  T[(a ^ 1) * 2 + 1][m] = z;
        } else {
            float2 acc = colA[0][(m ^ (m >> 1)) & 1];
            #pragma unroll
            for (int p = 1; p <= 5; p++)
                acc = cmul(acc, colA[p][((m >> p) ^ (m >> (p + 1))) & 1]);
            int h6 = (m >> 6) & 1, h7 = (m >> 7) & 1;
            float2 AH0 = cmul(acc, cmul(colA[6][h6 ^ h7],     colA[7][h7]));
            float2 AH1 = cmul(acc, cmul(colA[6][h6 ^ 1 ^ h7], colA[7][1 ^ h7]));
            int b2 = m & 1;                      // indicator [j8 = b]
            T[0 * 2 + b2][m] = AH0;  T[1 * 2 + b2][m] = AH1;
            T[0 * 2 + (b2 ^ 1)][m] = z;  T[1 * 2 + (b2 ^ 1)][m] = z;
        }
    }
    __syncthreads();

    // ---- full layer-1 gates on all 4 tables (table-wise butterflies) ----
    #pragma unroll
    for (int p = 0; p < 8; p++) {
        float2 ga = gl1[p][0], gb = gl1[p][1];
        int mask = 1 << p;
        for (int it = tid; it < 512; it += 256) {
            int k = it >> 7, pi = it & 127;
            int low = pi & (mask - 1);
            int m0 = ((pi ^ low) << 1) | low;
            int m1 = m0 | mask;
            float2 t0 = T[k][m0], t1 = T[k][m1];
            // new0 = a*t0 - conj(b)*t1 ; new1 = b*t0 + conj(a)*t1
            T[k][m0] = make_float2(
                ga.x * t0.x - ga.y * t0.y - (gb.x * t1.x + gb.y * t1.y),
                ga.x * t0.y + ga.y * t0.x - (gb.x * t1.y - gb.y * t1.x));
            T[k][m1] = make_float2(
                gb.x * t0.x - gb.y * t0.y + (ga.x * t1.x + ga.y * t1.y),
                gb.x * t0.y + gb.y * t0.x + (ga.x * t1.y - ga.y * t1.x));
        }
        __syncthreads();
    }

    // ---- write tables + diagonal prep ----
    if (side == 0) {
        #pragma unroll
        for (int k = 0; k < 4; k++)
            g_F4[(b * 4 + k) * 256 + tid] = T[k][tid];
        int m = tid;
        {   // slot 2: pure q0(L2) lo-product (both planes identical)
            float2 t = sel(q2[0], m & 1);
            #pragma unroll
            for (int p = 1; p <= 7; p++) t = cmul(t, sel(q2[p], (m >> p) & 1));
            g_TLt[((b * 4 + 2) * 2 + 0) * 256 + m] = t;
            g_TLt[((b * 4 + 2) * 2 + 1) * 256 + m] = t;
        }
        {   // slot 3: q0(L3) * p0(L2)-coupled (R13 formula)
            float2 acc = sel(q3[0], m & 1);
            #pragma unroll
            for (int p = 1; p <= 7; p++) acc = cmul(acc, sel(q3[p], (m >> p) & 1));
            #pragma unroll
            for (int p = 0; p <= 6; p++)
                acc = cmul(acc, sel(p2[p], ((m >> p) ^ (m >> (p + 1))) & 1));
            int m7 = (m >> 7) & 1;
            g_TLt[((b * 4 + 3) * 2 + 0) * 256 + m] = cmul(acc, sel(p2[7], m7));
            g_TLt[((b * 4 + 3) * 2 + 1) * 256 + m] = cmul(acc, sel(p2[7], m7 ^ 1));
        }
    } else {
        #pragma unroll
        for (int k = 0; k < 4; k++)
            g_G4[(b * 4 + k) * 256 + tid] = T[k][tid];
        int m = tid;
        {   // slot 2: pure q0(L2) hi-product (both b0 planes identical)
            float2 t = sel(q2[0], m & 1);
            #pragma unroll
            for (int p = 1; p <= 7; p++) t = cmul(t, sel(q2[p], (m >> p) & 1));
            g_THt[((b * 4 + 2) * 256 + m) * 2 + 0] = t;
            g_THt[((b * 4 + 2) * 256 + m) * 2 + 1] = t;
        }
        {   // slot 3: q0(L3) * p0(L2)-coupled (R13 formula)
            float2 acc = sel(q3[0], m & 1);
            #pragma unroll
            for (int p = 1; p <= 7; p++) acc = cmul(acc, sel(q3[p], (m >> p) & 1));
            #pragma unroll
            for (int p = 0; p <= 5; p++)
                acc = cmul(acc, sel(p2[p], ((m >> p) ^ (m >> (p + 1))) & 1));
            int h6 = (m >> 6) & 1, h7 = (m >> 7) & 1;
            #pragma unroll
            for (int b0 = 0; b0 < 2; b0++) {
                float2 a2 = cmul(acc, sel(p2[6], h6 ^ b0 ^ h7));
                a2 = cmul(a2, sel(p2[7], b0 ^ h7));
                g_THt[((b * 4 + 3) * 256 + m) * 2 + b0] = a2;
            }
        }
    }
}

// ---------------------------------------------------------------------------
// K_MAT: materialize the post-sigma1 state directly from the bond-4 MPS,
// with layer-2's pre-diagonal D2(L2) folded in. Write-only, fully coalesced.
// out[j] = D2(jlo,jhi) * sum_{k=0..3} F4_k[L(jlo,j8)] * G4_k[H(jhi,j0)]
// L(lo,b) = (lo^(lo>>1)) ^ (b<<7) ;  H(hi,a) = (hi^(hi>>1)) ^ (a?0xC0:0).
__global__ __launch_bounds__(512)
void k_mat(float2* __restrict__ st) {
    __shared__ float2 F4s[4][256], G4s[4][256];
    __shared__ float2 TL2s[256], TH2s[256];
    int b = blockIdx.y, seg = blockIdx.x, tid = threadIdx.x;

    for (int it = tid; it < 1024; it += 512) {
        F4s[it >> 8][it & 255] = g_F4[b * 1024 + it];
        G4s[it >> 8][it & 255] = g_G4[b * 1024 + it];
    }
    if (tid < 256) TL2s[tid] = g_TLt[(b * 4 + 2) * 512 + tid];
    else           TH2s[tid - 256] = g_THt[(b * 4 + 2) * 512 + (tid - 256) * 2];
    __syncthreads();

    float2* ob = st + (size_t)b * DIM;
    #pragma unroll 4
    for (int it = 0; it < 16; it++) {
        int j = seg * 8192 + it * 512 + tid;
        int jlo = j & 255, jhi = j >> 8;
        int ilo = (jlo ^ (jlo >> 1)) ^ ((jhi & 1) << 7);
        int ihi = (jhi ^ (jhi >> 1)) ^ ((jlo & 1) ? 0xC0 : 0);
        float2 amp = cmul(F4s[0][ilo], G4s[0][ihi]);
        float2 t;
        t = cmul(F4s[1][ilo], G4s[1][ihi]); amp.x += t.x; amp.y += t.y;
        t = cmul(F4s[2][ilo], G4s[2][ihi]); amp.x += t.x; amp.y += t.y;
        t = cmul(F4s[3][ilo], G4s[3][ihi]); amp.x += t.x; amp.y += t.y;
        float2 d = cmul(TL2s[jlo], TH2s[jhi]);
        ob[j] = cmul(amp, d);
    }
}

// ---------------------------------------------------------------------------
// KA: PURE rotations on lo bits 0..7 (diagonal applied by producer).
// Proven R13 version, UNCHANGED. grid (32, BATCH), 256 threads.
__global__ __launch_bounds__(256)
void k_low(int layer, float4* __restrict__ st4) {
    int b = blockIdx.y, tid = threadIdx.x;
    int wid = tid >> 5, lane = tid & 31;
    __shared__ float2 gcs[8];
    if (tid < 8) gcs[tid] = g_cs[(b * 4 + layer) * 16 + tid];
    __syncthreads();

    int hi = blockIdx.x * 8 + wid;
    float4* sbase = st4 + (size_t)b * (DIM / 2) + hi * 128;
    float4 v[4];
    #pragma unroll
    for (int r = 0; r < 4; r++) v[r] = sbase[r * 32 + lane];
    {
        float c = gcs[0].x, s = gcs[0].y;
        #pragma unroll
        for (int r = 0; r < 4; r++) {
            float4 a = v[r];
            v[r] = make_float4(c * a.x - s * a.z, c * a.y - s * a.w,
                               s * a.x + c * a.z, s * a.y + c * a.w);
        }
    }
    #pragma unroll
    for (int p = 1; p <= 5; p++) {
        float2 cp = gcs[p];
        float c = cp.x;
        float s = ((lane >> (p - 1)) & 1) ? cp.y : -cp.y;
        int msk = 1 << (p - 1);
        #pragma unroll
        for (int r = 0; r < 4; r++) {
            float px = __shfl_xor_sync(0xffffffffu, v[r].x, msk);
            float py = __shfl_xor_sync(0xffffffffu, v[r].y, msk);
            float pz = __shfl_xor_sync(0xffffffffu, v[r].z, msk);
            float pw = __shfl_xor_sync(0xffffffffu, v[r].w, msk);
            v[r].x = c * v[r].x + s * px;
            v[r].y = c * v[r].y + s * py;
            v[r].z = c * v[r].z + s * pz;
            v[r].w = c * v[r].w + s * pw;
        }
    }
    #pragma unroll
    for (int pb = 0; pb < 2; pb++) {
        int m = 1 << pb;
        float2 cp = gcs[6 + pb];
        float c = cp.x, s = cp.y;
        #pragma unroll
        for (int r = 0; r < 4; r++)
            if (!(r & m)) {
                float4 A = v[r], B = v[r + m];
                v[r]     = make_float4(c * A.x - s * B.x, c * A.y - s * B.y,
                                       c * A.z - s * B.z, c * A.w - s * B.w);
                v[r + m] = make_float4(s * A.x + c * B.x, s * A.y + c * B.y,
                                       s * A.z + c * B.z, s * A.w + c * B.w);
            }
    }
    #pragma unroll
    for (int r = 0; r < 4; r++) sbase[r * 32 + lane] = v[r];
}

// ---------------------------------------------------------------------------
// KB: rotations on hi bits 0..7 (zero-shuffle 3-phase). Non-final: scatter
// with NEXT layer's combined diagonal (slot base+1). FINAL: signed-marginal
// readout. Proven R13 version, UNCHANGED. 512 threads, grid (16, BATCH).
template <bool FINAL>
__global__ __launch_bounds__(512)
void k_high(int layer, const float2* __restrict__ in,
            float2* __restrict__ outst, float* __restrict__ part) {
    __shared__ float2 tile[16 * 257];
    __shared__ float2 dTL[512];
    __shared__ float2 dTH[512];
    int b = blockIdx.y, logrp = blockIdx.x, tid = threadIdx.x;
    int base = b * 4 + layer;
    int lo4 = tid & 15, s = tid >> 4;
    float2 u[8];

    if (!FINAL) {
        int nbase = base + 1;
        dTL[tid] = g_TLt[nbase * 512 + tid];
        dTH[tid] = g_THt[nbase * 512 + tid];
    }

    {
        const float2* gb = in + (size_t)b * DIM + (s << 3) * 256 + logrp * 16 + lo4;
        #pragma unroll
        for (int k = 0; k < 8; k++) u[k] = gb[k * 256];
        #pragma unroll
        for (int p = 0; p < 3; p++) {
            float2 cp = g_cs[base * 16 + 8 + p];
            int m = 1 << p;
            #pragma unroll
            for (int k = 0; k < 8; k++)
                if (!(k & m)) rot2(u[k], u[k + m], cp.x, cp.y);
        }
        #pragma unroll
        for (int k = 0; k < 8; k++)
            tile[lo4 * 257 + (s << 3) + k] = u[k];
    }
    __syncthreads();

    {
        int c = s & 7, d = s >> 3;
        int hbase = (d << 6) | c;
        #pragma unroll
        for (int m = 0; m < 8; m++) u[m] = tile[lo4 * 257 + hbase + (m << 3)];
        #pragma unroll
        for (int p = 0; p < 3; p++) {
            float2 cp = g_cs[base * 16 + 11 + p];
            int mm = 1 << p;
            #pragma unroll
            for (int m = 0; m < 8; m++)
                if (!(m & mm)) rot2(u[m], u[m + mm], cp.x, cp.y);
        }
        #pragma unroll
        for (int m = 0; m < 8; m++) tile[lo4 * 257 + hbase + (m << 3)] = u[m];
    }
    __syncthreads();

    {
        int hbase = s << 1;
        #pragma unroll
        for (int n = 0; n < 8; n++)
            u[n] = tile[lo4 * 257 + hbase + ((n >> 1) << 6) + (n & 1)];
        #pragma unroll
        for (int p = 0; p < 2; p++) {
            float2 cp = g_cs[base * 16 + 14 + p];
            int mm = 2 << p;
            #pragma unroll
            for (int n = 0; n < 8; n++)
                if (!(n & mm)) rot2(u[n], u[n + mm], cp.x, cp.y);
        }
    }

    if (!FINAL) {
        int jbase = sigma16((s << 9) | (logrp << 4) | lo4);
        float2* ob = outst + (size_t)b * DIM;
        #pragma unroll
        for (int n = 0; n < 8; n++) {
            int j = jbase ^ sigma16(((n & 1) << 8) | ((n >> 1) << 14));
            int jlo = j & 255, jhi = j >> 8;
            float2 d = cmul(dTL[((jhi & 1) << 8) | jlo], dTH[(jhi << 1) | (j & 1)]);
            ob[j] = cmul(u[n], d);
        }
    } else {
        __syncthreads();
        float* pf = (float*)tile;
        #pragma unroll
        for (int n = 0; n < 8; n++) {
            int hi = ((n >> 1) << 6) | (s << 1) | (n & 1);
            pf[lo4 * 257 + hi] = u[n].x * u[n].x + u[n].y * u[n].y;
        }
        __syncthreads();

        int wid = tid >> 5, lane = tid & 31;
        float spv[8], smv[8];
        if (tid < 256) {
            #pragma unroll
            for (int r = 0; r < 8; r++) {
                float p0 = pf[(wid * 2)     * 257 + r * 32 + lane];
                float p1 = pf[(wid * 2 + 1) * 257 + r * 32 + lane];
                spv[r] = p0 + p1; smv[r] = p0 - p1;
            }
        }
        __syncthreads();
        float* S  = pf;
        float* S2 = pf + 4096;
        if (tid < 256) {
            #pragma unroll
            for (int r = 0; r < 8; r++) {
                S[wid * 256 + r * 32 + lane]        = spv[r];
                S[2048 + wid * 256 + r * 32 + lane] = smv[r];
            }
        }
        __syncthreads();

        if (tid < 256) {
            float V0 = 0.f, V1 = 0.f, V2 = 0.f, V3 = 0.f, V4 = 0.f;
            #pragma unroll
            for (int w2 = 0; w2 < 8; w2++) {
                float sp = S[w2 * 256 + tid];
                float sm = S[2048 + w2 * 256 + tid];
                int pw  = __popc(w2) & 1;
                int pw2 = __popc(w2 >> 1) & 1;
                int pw3 = (w2 >> 2) & 1;
                V4 += sp;
                V1 += pw  ? -sp : sp;
                V2 += pw2 ? -sp : sp;
                V3 += pw3 ? -sp : sp;
                V0 += pw  ? -sm : sm;
            }
            float A[12];
            int t = tid;
            int pfb = __popc(t) & 1;
            #pragma unroll
            for (int k = 0; k < 7; k++)
                A[k] = (__popc(t >> k) & 1) ? -V4 : V4;
            A[7]  = pfb ? -V0 : V0;
            A[8]  = pfb ? -V1 : V1;
            A[9]  = pfb ? -V2 : V2;
            A[10] = pfb ? -V3 : V3;
            A[11] = (__popc(t & 0x7F) & 1) ? -V0 : V0;
            #pragma unroll
            for (int k = 0; k < 12; k++) {
                float a = A[k];
                #pragma unroll
                for (int o = 16; o; o >>= 1) a += __shfl_down_sync(0xffffffffu, a, o);
                if (lane == 0) S2[wid * 12 + k] = a;
            }
        }
        __syncthreads();
        if (tid < 12) {
            float sum = 0.f;
            #pragma unroll
            for (int w2 = 0; w2 < 8; w2++) sum += S2[w2 * 12 + tid];
            S2[96 + tid] = sum;
        }
        __syncthreads();
        if (tid < 16) {
            const float* R = S2 + 96;
            int q = tid, lg = logrp;
            float sgnAll = (__popc(lg) & 1) ? -1.f : 1.f;
            float val;
            if (q == 0)        val = sgnAll * R[11];
            else if (q < 8)    val = R[7 - q];
            else if (q < 12) {
                int P = 15 - q;
                val = ((__popc(lg >> (P - 4)) & 1) ? -1.f : 1.f) * R[0];
            } else {
                int P = 15 - q;
                val = sgnAll * R[7 + P];
            }
            part[(b * 16 + lg) * 16 + q] = val;
        }
    }
}

// Final deterministic reduction of partials -> out[b][q]
__global__ __launch_bounds__(256)
void k_reduce(const float* __restrict__ part, float* __restrict__ out) {
    int idx = blockIdx.x * 256 + threadIdx.x;
    int b = idx >> 4, q = idx & 15;
    float s = 0.f;
    #pragma unroll
    for (int gp = 0; gp < 16; gp++) s += part[(b * 16 + gp) * 16 + q];
    out[idx] = s;
}

// ---------------------------------------------------------------------------
extern "C" void kernel_launch(void* const* d_in, const int* in_sizes, int n_in,
                              void* d_out, int out_size) {
    const float* x = (const float*)d_in[0];
    const float* w = (const float*)d_in[1];
    if (n_in >= 2 && in_sizes[0] == 192) { const float* t = x; x = w; w = t; }
    float* out = (float*)d_out;

    float4 *s0, *s1; float* part;
    cudaGetSymbolAddress((void**)&s0, g_state0);
    cudaGetSymbolAddress((void**)&s1, g_state1);
    cudaGetSymbolAddress((void**)&part, g_partial);

    k_tab<<<dim3(2, BATCH), 256>>>(x, w);
    k_mat<<<dim3(8, BATCH), 512>>>((float2*)s0);

    k_low <<<dim3(32, BATCH), 256>>>(2, s0);
    k_high<false><<<dim3(16, BATCH), 512>>>(2, (const float2*)s0, (float2*)s1, nullptr);

    k_low <<<dim3(32, BATCH), 256>>>(3, s1);
    k_high<true> <<<dim3(16, BATCH), 512>>>(3, (const float2*)s1, nullptr, part);

    k_reduce<<<8, 256>>>(part, out);
}

// round 16
// speedup vs baseline: 1.4236x; 1.0686x over previous
#include <cuda_runtime.h>
#include <cstdint>

#define N_QUBITS 16
#define DIM 65536
#define BATCH 128

// Scratch state buffers (device globals: allocation-free rule).
__device__ __align__(16) float4 g_state0[BATCH * DIM / 2];
__device__ __align__(16) float4 g_state1[BATCH * DIM / 2];
__device__ float g_partial[BATCH * 16 * 16];   // [b][loGroup][q]

// Precomputed per-(batch,layer) gate data.
__device__ float2 g_cs  [BATCH * 4 * 16];          // rotation (c,s) per bit p (slots 2,3)
__device__ __align__(16) float2 g_TLt [BATCH * 4 * 2 * 256];   // TL[b8][lo] (slot 3 used)
__device__ __align__(16) float2 g_THt [BATCH * 4 * 256 * 2];   // TH[hi][b0] (slots 2,3)

// MPS bond-4 tables after layer-0 + sigma0 + full layer-1 gates.
// F side: pre-permuted to j-index and folded with TL2:
//   g_F4p[((b*2 + j8)*256 + jlo)*4 + k] = F_k[L(jlo,j8)] * TL2[jlo]
__device__ __align__(16) float2 g_F4p[BATCH * 2 * 256 * 4];
// G side: i-indexed (lazy H map at use site).
__device__ __align__(16) float2 g_G4 [BATCH * 4 * 256];

// ---------------------------------------------------------------------------
__device__ __forceinline__ float2 cmul(float2 a, float2 b) {
    return make_float2(a.x * b.x - a.y * b.y, a.x * b.y + a.y * b.x);
}
__device__ __forceinline__ float2 sel(float2 v, int bit) {
    return bit ? make_float2(v.x, -v.y) : v;
}
__device__ __forceinline__ void rot2(float2& A, float2& B, float c, float s) {
    float2 a = A, b = B;
    A = make_float2(c * a.x - s * b.x, c * a.y - s * b.y);
    B = make_float2(s * a.x + c * b.x, s * a.y + c * b.y);
}

// CNOT-ring permutation sigma (GF(2)-linear).
__device__ __forceinline__ int sigma16(int i) {
    int t = i;
    t ^= t >> 1; t ^= t >> 2; t ^= t >> 4; t ^= t >> 8;
    int b15 = (t ^ (i >> 15)) & 1;
    return (t & 0x7FFF) | (b15 << 15);
}

// ---------------------------------------------------------------------------
// First column of G = Rot(phi,theta,omega) @ RY(x): G00=(g0,g1), G10=(g4,g5).
__device__ void gate_col(const float* __restrict__ x,
                         const float* __restrict__ w,
                         int b, int l, int q,
                         float& g0, float& g1, float& g4, float& g5) {
    float xv  = x[(b * 4 + l) * 16 + q];
    const float* wp = w + (l * 16 + q) * 3;
    float phi = wp[0], th = wp[1], om = wp[2];
    float ct, st, cr, sr, sp, cp, sm, cm;
    sincosf(0.5f * th, &st, &ct);
    sincosf(0.5f * xv, &sr, &cr);
    sincosf(0.5f * (phi + om), &sp, &cp);
    sincosf(0.5f * (phi - om), &sm, &cm);
    float m00r =  cp * ct, m00i = -sp * ct;
    float m01r = -cm * st, m01i = -sm * st;
    float m10r =  cm * st, m10i = -sm * st;
    float m11r =  cp * ct, m11i =  sp * ct;
    g0 = m00r * cr + m01r * sr;  g1 = m00i * cr + m01i * sr;
    g4 = m10r * cr + m11r * sr;  g5 = m10i * cr + m11i * sr;
}

__device__ void gate_decomp(const float* __restrict__ x,
                            const float* __restrict__ w,
                            int b, int l, int q,
                            float2& cs, float2& q0, float2& p0) {
    float g0, g1, g4, g5;
    gate_col(x, w, b, l, q, g0, g1, g4, g5);
    float ca = sqrtf(g0 * g0 + g1 * g1);
    float sb = sqrtf(g4 * g4 + g5 * g5);
    float au = atan2f(g1, g0);
    float av = atan2f(g5, g4);
    float s1, c1, s2, c2;
    sincosf(0.5f * (au + av), &s1, &c1);
    sincosf(0.5f * (au - av), &s2, &c2);
    cs = make_float2(ca, sb);
    q0 = make_float2(c1, s1);
    p0 = make_float2(c2, s2);
}

// ---------------------------------------------------------------------------
// K_TAB: grid (2, BATCH). Side 0 = lo/F tables (+TL2-folded pre-permute),
// side 1 = hi/G tables. Also layer-2/3 rotation coeffs + diagonal tables.
__global__ __launch_bounds__(256)
void k_tab(const float* __restrict__ x, const float* __restrict__ w) {
    int b = blockIdx.y, side = blockIdx.x, tid = threadIdx.x;
    __shared__ float2 colA[8][2];
    __shared__ float2 gl1[8][2];
    __shared__ float2 q2[8], p2[8], q3[8];
    __shared__ float2 T[4][256];

    if (side == 0) {
        if (tid < 8) {
            float a0, a1, b0, b1;
            gate_col(x, w, b, 0, 15 - tid, a0, a1, b0, b1);
            colA[tid][0] = make_float2(a0, a1);
            colA[tid][1] = make_float2(b0, b1);
            gate_col(x, w, b, 1, 15 - tid, a0, a1, b0, b1);
            gl1[tid][0] = make_float2(a0, a1);
            gl1[tid][1] = make_float2(b0, b1);
        } else if (tid < 16) {
            int p = tid - 8;
            float2 cs, q0, p0;
            gate_decomp(x, w, b, 2, 15 - p, cs, q0, p0);
            g_cs[(b * 4 + 2) * 16 + p] = cs;
            q2[p] = q0; p2[p] = p0;
        } else if (tid < 24) {
            int p = tid - 16;
            float2 cs, q0, p0;
            gate_decomp(x, w, b, 3, 15 - p, cs, q0, p0);
            g_cs[(b * 4 + 3) * 16 + p] = cs;
            q3[p] = q0;
        }
    } else {
        if (tid < 8) {
            float a0, a1, b0, b1;
            gate_col(x, w, b, 0, 7 - tid, a0, a1, b0, b1);
            colA[tid][0] = make_float2(a0, a1);
            colA[tid][1] = make_float2(b0, b1);
            gate_col(x, w, b, 1, 7 - tid, a0, a1, b0, b1);
            gl1[tid][0] = make_float2(a0, a1);
            gl1[tid][1] = make_float2(b0, b1);
        } else if (tid < 16) {
            int p = tid - 8;
            float2 cs, q0, p0;
            gate_decomp(x, w, b, 2, 7 - p, cs, q0, p0);
            g_cs[(b * 4 + 2) * 16 + 8 + p] = cs;
            q2[p] = q0; p2[p] = p0;
        } else if (tid < 24) {
            int p = tid - 16;
            float2 cs, q0, p0;
            gate_decomp(x, w, b, 3, 7 - p, cs, q0, p0);
            g_cs[(b * 4 + 3) * 16 + 8 + p] = cs;
            q3[p] = q0;
        }
    }
    __syncthreads();

    // ---- K=4 indicator tables (i-indexed, sigma0 maps inside) ----
    {
        int m = tid;
        float2 z = make_float2(0.f, 0.f);
        if (side == 0) {
            float2 acc = colA[0][(m ^ (m >> 1)) & 1];
            #pragma unroll
            for (int p = 1; p <= 6; p++)
                acc = cmul(acc, colA[p][((m >> p) ^ (m >> (p + 1))) & 1]);
            int m7 = (m >> 7) & 1;
            float2 AL0 = cmul(acc, colA[7][m7]);
            float2 AL1 = cmul(acc, colA[7][m7 ^ 1]);
            int a = m & 1;
            T[a * 2 + 0][m] = AL0;  T[a * 2 + 1][m] = AL1;
            T[(a ^ 1) * 2 + 0][m] = z;  T[(a ^ 1) * 2 + 1][m] = z;
        } else {
            float2 acc = colA[0][(m ^ (m >> 1)) & 1];
            #pragma unroll
            for (int p = 1; p <= 5; p++)
                acc = cmul(acc, colA[p][((m >> p) ^ (m >> (p + 1))) & 1]);
            int h6 = (m >> 6) & 1, h7 = (m >> 7) & 1;
            float2 AH0 = cmul(acc, cmul(colA[6][h6 ^ h7],     colA[7][h7]));
            float2 AH1 = cmul(acc, cmul(colA[6][h6 ^ 1 ^ h7], colA[7][1 ^ h7]));
            int b2 = m & 1;
            T[0 * 2 + b2][m] = AH0;  T[1 * 2 + b2][m] = AH1;
            T[0 * 2 + (b2 ^ 1)][m] = z;  T[1 * 2 + (b2 ^ 1)][m] = z;
        }
    }
    __syncthreads();

    // ---- full layer-1 gates on all 4 tables ----
    #pragma unroll
    for (int p = 0; p < 8; p++) {
        float2 ga = gl1[p][0], gb = gl1[p][1];
        int mask = 1 << p;
        for (int it = tid; it < 512; it += 256) {
            int k = it >> 7, pi = it & 127;
            int low = pi & (mask - 1);
            int m0 = ((pi ^ low) << 1) | low;
            int m1 = m0 | mask;
            float2 t0 = T[k][m0], t1 = T[k][m1];
            T[k][m0] = make_float2(
                ga.x * t0.x - ga.y * t0.y - (gb.x * t1.x + gb.y * t1.y),
                ga.x * t0.y + ga.y * t0.x - (gb.x * t1.y - gb.y * t1.x));
            T[k][m1] = make_float2(
                gb.x * t0.x - gb.y * t0.y + (ga.x * t1.x + ga.y * t1.y),
                gb.x * t0.y + gb.y * t0.x + (ga.x * t1.y - ga.y * t1.x));
        }
        __syncthreads();
    }

    // ---- write tables + diagonal prep ----
    if (side == 0) {
        int m = tid;
        // TL2 (pure q0(L2)): folded into F4p
        float2 tl2 = sel(q2[0], m & 1);
        #pragma unroll
        for (int p = 1; p <= 7; p++) tl2 = cmul(tl2, sel(q2[p], (m >> p) & 1));
        #pragma unroll
        for (int b8 = 0; b8 < 2; b8++) {
            int ilo = (m ^ (m >> 1)) ^ (b8 << 7);
            #pragma unroll
            for (int k = 0; k < 4; k++)
                g_F4p[((b * 2 + b8) * 256 + m) * 4 + k] = cmul(T[k][ilo], tl2);
        }
        {   // slot 3: q0(L3) * p0(L2)-coupled (R13 formula)
            float2 acc = sel(q3[0], m & 1);
            #pragma unroll
            for (int p = 1; p <= 7; p++) acc = cmul(acc, sel(q3[p], (m >> p) & 1));
            #pragma unroll
            for (int p = 0; p <= 6; p++)
                acc = cmul(acc, sel(p2[p], ((m >> p) ^ (m >> (p + 1))) & 1));
            int m7 = (m >> 7) & 1;
            g_TLt[((b * 4 + 3) * 2 + 0) * 256 + m] = cmul(acc, sel(p2[7], m7));
            g_TLt[((b * 4 + 3) * 2 + 1) * 256 + m] = cmul(acc, sel(p2[7], m7 ^ 1));
        }
    } else {
        #pragma unroll
        for (int k = 0; k < 4; k++)
            g_G4[(b * 4 + k) * 256 + tid] = T[k][tid];
        int m = tid;
        {   // slot 2: pure q0(L2) hi-product (both b0 planes identical)
            float2 t = sel(q2[0], m & 1);
            #pragma unroll
            for (int p = 1; p <= 7; p++) t = cmul(t, sel(q2[p], (m >> p) & 1));
            g_THt[((b * 4 + 2) * 256 + m) * 2 + 0] = t;
            g_THt[((b * 4 + 2) * 256 + m) * 2 + 1] = t;
        }
        {   // slot 3: q0(L3) * p0(L2)-coupled
            float2 acc = sel(q3[0], m & 1);
            #pragma unroll
            for (int p = 1; p <= 7; p++) acc = cmul(acc, sel(q3[p], (m >> p) & 1));
            #pragma unroll
            for (int p = 0; p <= 5; p++)
                acc = cmul(acc, sel(p2[p], ((m >> p) ^ (m >> (p + 1))) & 1));
            int h6 = (m >> 6) & 1, h7 = (m >> 7) & 1;
            #pragma unroll
            for (int b0 = 0; b0 < 2; b0++) {
                float2 a2 = cmul(acc, sel(p2[6], h6 ^ b0 ^ h7));
                a2 = cmul(a2, sel(p2[7], b0 ^ h7));
                g_THt[((b * 4 + 3) * 256 + m) * 2 + b0] = a2;
            }
        }
    }
}

// ---------------------------------------------------------------------------
// K_MATLOW: fused materialize (bond-4, D2(L2) folded) + layer-2 lo gates.
// grid (32, BATCH), 256 threads. Per warp: hi fixed; amp = sum_k c[k][j0] *
// F4p[hi&1][jlo][k] (8 warp constants), then the proven k_low gate body.
// Smem tile: 5-float4 row stride -> conflict-free LDS.128 in all phases.
__global__ __launch_bounds__(256)
void k_matlow(float4* __restrict__ st4) {
    __shared__ __align__(16) float4 Fp4[2 * 128 * 5];   // 20.5 KB
    __shared__ float2 gcs[8];
    int b = blockIdx.y, tid = threadIdx.x;
    int wid = tid >> 5, lane = tid & 31;

    if (tid < 8) gcs[tid] = g_cs[(b * 4 + 2) * 16 + tid];
    {   // load F4p: global rows of 4 float4 -> smem rows of stride 5
        const float4* src = (const float4*)(g_F4p + b * 2048);
        #pragma unroll
        for (int i = tid; i < 1024; i += 256) {
            int row = i >> 2, sub = i & 3;
            Fp4[row * 5 + sub] = src[i];
        }
    }
    __syncthreads();

    int hi = blockIdx.x * 8 + wid;
    // 8 warp constants c[k][e] = G_k[H(hi,e)] * TH2[hi]
    float2 c[4][2];
    {
        float2 th2 = g_THt[(b * 4 + 2) * 512 + hi * 2];
        int h0 = (hi ^ (hi >> 1)) & 255;
        #pragma unroll
        for (int k = 0; k < 4; k++) {
            c[k][0] = cmul(g_G4[(b * 4 + k) * 256 + h0],          th2);
            c[k][1] = cmul(g_G4[(b * 4 + k) * 256 + (h0 ^ 0xC0)], th2);
        }
    }

    const float4* Fbase = Fp4 + (hi & 1) * 640;
    float4 v[4];
    #pragma unroll
    for (int r = 0; r < 4; r++) {
        int p = r * 32 + lane;                 // jlo pair index (m = 2p)
        const float4* f = Fbase + p * 5;
        float4 f0 = f[0], f1 = f[1], f2 = f[2], f3 = f[3];
        // even jlo (e=0): k0,k1 in f0; k2,k3 in f1
        float2 A;
        A.x = c[0][0].x * f0.x - c[0][0].y * f0.y
            + c[1][0].x * f0.z - c[1][0].y * f0.w
            + c[2][0].x * f1.x - c[2][0].y * f1.y
            + c[3][0].x * f1.z - c[3][0].y * f1.w;
        A.y = c[0][0].x * f0.y + c[0][0].y * f0.x
            + c[1][0].x * f0.w + c[1][0].y * f0.z
            + c[2][0].x * f1.y + c[2][0].y * f1.x
            + c[3][0].x * f1.w + c[3][0].y * f1.z;
        // odd jlo (e=1): k0,k1 in f2; k2,k3 in f3
        float2 B;
        B.x = c[0][1].x * f2.x - c[0][1].y * f2.y
            + c[1][1].x * f2.z - c[1][1].y * f2.w
            + c[2][1].x * f3.x - c[2][1].y * f3.y
            + c[3][1].x * f3.z - c[3][1].y * f3.w;
        B.y = c[0][1].x * f2.y + c[0][1].y * f2.x
            + c[1][1].x * f2.w + c[1][1].y * f2.z
            + c[2][1].x * f3.y + c[2][1].y * f3.x
            + c[3][1].x * f3.w + c[3][1].y * f3.z;
        v[r] = make_float4(A.x, A.y, B.x, B.y);
    }

    // ---- proven k_low gate body (layer-2 lo rotations) ----
    {
        float cc = gcs[0].x, ss = gcs[0].y;
        #pragma unroll
        for (int r = 0; r < 4; r++) {
            float4 a = v[r];
            v[r] = make_float4(cc * a.x - ss * a.z, cc * a.y - ss * a.w,
                               ss * a.x + cc * a.z, ss * a.y + cc * a.w);
        }
    }
    #pragma unroll
    for (int p = 1; p <= 5; p++) {
        float2 cp = gcs[p];
        float cc = cp.x;
        float ss = ((lane >> (p - 1)) & 1) ? cp.y : -cp.y;
        int msk = 1 << (p - 1);
        #pragma unroll
        for (int r = 0; r < 4; r++) {
            float px = __shfl_xor_sync(0xffffffffu, v[r].x, msk);
            float py = __shfl_xor_sync(0xffffffffu, v[r].y, msk);
            float pz = __shfl_xor_sync(0xffffffffu, v[r].z, msk);
            float pw = __shfl_xor_sync(0xffffffffu, v[r].w, msk);
            v[r].x = cc * v[r].x + ss * px;
            v[r].y = cc * v[r].y + ss * py;
            v[r].z = cc * v[r].z + ss * pz;
            v[r].w = cc * v[r].w + ss * pw;
        }
    }
    #pragma unroll
    for (int pb = 0; pb < 2; pb++) {
        int m = 1 << pb;
        float2 cp = gcs[6 + pb];
        float cc = cp.x, ss = cp.y;
        #pragma unroll
        for (int r = 0; r < 4; r++)
            if (!(r & m)) {
                float4 A = v[r], B = v[r + m];
                v[r]     = make_float4(cc * A.x - ss * B.x, cc * A.y - ss * B.y,
                                       cc * A.z - ss * B.z, cc * A.w - ss * B.w);
                v[r + m] = make_float4(ss * A.x + cc * B.x, ss * A.y + cc * B.y,
                                       ss * A.z + cc * B.z, ss * A.w + cc * B.w);
            }
    }
    float4* sbase = st4 + (size_t)b * (DIM / 2) + hi * 128;
    #pragma unroll
    for (int r = 0; r < 4; r++) sbase[r * 32 + lane] = v[r];
}

// ---------------------------------------------------------------------------
// KA: PURE rotations on lo bits 0..7 (layer 3). Proven version, UNCHANGED.
__global__ __launch_bounds__(256)
void k_low(int layer, float4* __restrict__ st4) {
    int b = blockIdx.y, tid = threadIdx.x;
    int wid = tid >> 5, lane = tid & 31;
    __shared__ float2 gcs[8];
    if (tid < 8) gcs[tid] = g_cs[(b * 4 + layer) * 16 + tid];
    __syncthreads();

    int hi = blockIdx.x * 8 + wid;
    float4* sbase = st4 + (size_t)b * (DIM / 2) + hi * 128;
    float4 v[4];
    #pragma unroll
    for (int r = 0; r < 4; r++) v[r] = sbase[r * 32 + lane];
    {
        float c = gcs[0].x, s = gcs[0].y;
        #pragma unroll
        for (int r = 0; r < 4; r++) {
            float4 a = v[r];
            v[r] = make_float4(c * a.x - s * a.z, c * a.y - s * a.w,
                               s * a.x + c * a.z, s * a.y + c * a.w);
        }
    }
    #pragma unroll
    for (int p = 1; p <= 5; p++) {
        float2 cp = gcs[p];
        float c = cp.x;
        float s = ((lane >> (p - 1)) & 1) ? cp.y : -cp.y;
        int msk = 1 << (p - 1);
        #pragma unroll
        for (int r = 0; r < 4; r++) {
            float px = __shfl_xor_sync(0xffffffffu, v[r].x, msk);
            float py = __shfl_xor_sync(0xffffffffu, v[r].y, msk);
            float pz = __shfl_xor_sync(0xffffffffu, v[r].z, msk);
            float pw = __shfl_xor_sync(0xffffffffu, v[r].w, msk);
            v[r].x = c * v[r].x + s * px;
            v[r].y = c * v[r].y + s * py;
            v[r].z = c * v[r].z + s * pz;
            v[r].w = c * v[r].w + s * pw;
        }
    }
    #pragma unroll
    for (int pb = 0; pb < 2; pb++) {
        int m = 1 << pb;
        float2 cp = gcs[6 + pb];
        float c = cp.x, s = cp.y;
        #pragma unroll
        for (int r = 0; r < 4; r++)
            if (!(r & m)) {
                float4 A = v[r], B = v[r + m];
                v[r]     = make_float4(c * A.x - s * B.x, c * A.y - s * B.y,
                                       c * A.z - s * B.z, c * A.w - s * B.w);
                v[r + m] = make_float4(s * A.x + c * B.x, s * A.y + c * B.y,
                                       s * A.z + c * B.z, s * A.w + c * B.w);
            }
    }
    #pragma unroll
    for (int r = 0; r < 4; r++) sbase[r * 32 + lane] = v[r];
}

// ---------------------------------------------------------------------------
// KB: rotations on hi bits 0..7 (zero-shuffle 3-phase). Proven, UNCHANGED.
template <bool FINAL>
__global__ __launch_bounds__(512)
void k_high(int layer, const float2* __restrict__ in,
            float2* __restrict__ outst, float* __restrict__ part) {
    __shared__ float2 tile[16 * 257];
    __shared__ float2 dTL[512];
    __shared__ float2 dTH[512];
    int b = blockIdx.y, logrp = blockIdx.x, tid = threadIdx.x;
    int base = b * 4 + layer;
    int lo4 = tid & 15, s = tid >> 4;
    float2 u[8];

    if (!FINAL) {
        int nbase = base + 1;
        dTL[tid] = g_TLt[nbase * 512 + tid];
        dTH[tid] = g_THt[nbase * 512 + tid];
    }

    {
        const float2* gb = in + (size_t)b * DIM + (s << 3) * 256 + logrp * 16 + lo4;
        #pragma unroll
        for (int k = 0; k < 8; k++) u[k] = gb[k * 256];
        #pragma unroll
        for (int p = 0; p < 3; p++) {
            float2 cp = g_cs[base * 16 + 8 + p];
            int m = 1 << p;
            #pragma unroll
            for (int k = 0; k < 8; k++)
                if (!(k & m)) rot2(u[k], u[k + m], cp.x, cp.y);
        }
        #pragma unroll
        for (int k = 0; k < 8; k++)
            tile[lo4 * 257 + (s << 3) + k] = u[k];
    }
    __syncthreads();

    {
        int c = s & 7, d = s >> 3;
        int hbase = (d << 6) | c;
        #pragma unroll
        for (int m = 0; m < 8; m++) u[m] = tile[lo4 * 257 + hbase + (m << 3)];
        #pragma unroll
        for (int p = 0; p < 3; p++) {
            float2 cp = g_cs[base * 16 + 11 + p];
            int mm = 1 << p;
            #pragma unroll
            for (int m = 0; m < 8; m++)
                if (!(m & mm)) rot2(u[m], u[m + mm], cp.x, cp.y);
        }
        #pragma unroll
        for (int m = 0; m < 8; m++) tile[lo4 * 257 + hbase + (m << 3)] = u[m];
    }
    __syncthreads();

    {
        int hbase = s << 1;
        #pragma unroll
        for (int n = 0; n < 8; n++)
            u[n] = tile[lo4 * 257 + hbase + ((n >> 1) << 6) + (n & 1)];
        #pragma unroll
        for (int p = 0; p < 2; p++) {
            float2 cp = g_cs[base * 16 + 14 + p];
            int mm = 2 << p;
            #pragma unroll
            for (int n = 0; n < 8; n++)
                if (!(n & mm)) rot2(u[n], u[n + mm], cp.x, cp.y);
        }
    }

    if (!FINAL) {
        int jbase = sigma16((s << 9) | (logrp << 4) | lo4);
        float2* ob = outst + (size_t)b * DIM;
        #pragma unroll
        for (int n = 0; n < 8; n++) {
            int j = jbase ^ sigma16(((n & 1) << 8) | ((n >> 1) << 14));
            int jlo = j & 255, jhi = j >> 8;
            float2 d = cmul(dTL[((jhi & 1) << 8) | jlo], dTH[(jhi << 1) | (j & 1)]);
            ob[j] = cmul(u[n], d);
        }
    } else {
        __syncthreads();
        float* pf = (float*)tile;
        #pragma unroll
        for (int n = 0; n < 8; n++) {
            int hi = ((n >> 1) << 6) | (s << 1) | (n & 1);
            pf[lo4 * 257 + hi] = u[n].x * u[n].x + u[n].y * u[n].y;
        }
        __syncthreads();

        int wid = tid >> 5, lane = tid & 31;
        float spv[8], smv[8];
        if (tid < 256) {
            #pragma unroll
            for (int r = 0; r < 8; r++) {
                float p0 = pf[(wid * 2)     * 257 + r * 32 + lane];
                float p1 = pf[(wid * 2 + 1) * 257 + r * 32 + lane];
                spv[r] = p0 + p1; smv[r] = p0 - p1;
            }
        }
        __syncthreads();
        float* S  = pf;
        float* S2 = pf + 4096;
        if (tid < 256) {
            #pragma unroll
            for (int r = 0; r < 8; r++) {
                S[wid * 256 + r * 32 + lane]        = spv[r];
                S[2048 + wid * 256 + r * 32 + lane] = smv[r];
            }
        }
        __syncthreads();

        if (tid < 256) {
            float V0 = 0.f, V1 = 0.f, V2 = 0.f, V3 = 0.f, V4 = 0.f;
            #pragma unroll
            for (int w2 = 0; w2 < 8; w2++) {
                float sp = S[w2 * 256 + tid];
                float sm = S[2048 + w2 * 256 + tid];
                int pw  = __popc(w2) & 1;
                int pw2 = __popc(w2 >> 1) & 1;
                int pw3 = (w2 >> 2) & 1;
                V4 += sp;
                V1 += pw  ? -sp : sp;
                V2 += pw2 ? -sp : sp;
                V3 += pw3 ? -sp : sp;
                V0 += pw  ? -sm : sm;
            }
            float A[12];
            int t = tid;
            int pfb = __popc(t) & 1;
            #pragma unroll
            for (int k = 0; k < 7; k++)
                A[k] = (__popc(t >> k) & 1) ? -V4 : V4;
            A[7]  = pfb ? -V0 : V0;
            A[8]  = pfb ? -V1 : V1;
            A[9]  = pfb ? -V2 : V2;
            A[10] = pfb ? -V3 : V3;
            A[11] = (__popc(t & 0x7F) & 1) ? -V0 : V0;
            #pragma unroll
            for (int k = 0; k < 12; k++) {
                float a = A[k];
                #pragma unroll
                for (int o = 16; o; o >>= 1) a += __shfl_down_sync(0xffffffffu, a, o);
                if (lane == 0) S2[wid * 12 + k] = a;
            }
        }
        __syncthreads();
        if (tid < 12) {
            float sum = 0.f;
            #pragma unroll
            for (int w2 = 0; w2 < 8; w2++) sum += S2[w2 * 12 + tid];
            S2[96 + tid] = sum;
        }
        __syncthreads();
        if (tid < 16) {
            const float* R = S2 + 96;
            int q = tid, lg = logrp;
            float sgnAll = (__popc(lg) & 1) ? -1.f : 1.f;
            float val;
            if (q == 0)        val = sgnAll * R[11];
            else if (q < 8)    val = R[7 - q];
            else if (q < 12) {
                int P = 15 - q;
                val = ((__popc(lg >> (P - 4)) & 1) ? -1.f : 1.f) * R[0];
            } else {
                int P = 15 - q;
                val = sgnAll * R[7 + P];
            }
            part[(b * 16 + lg) * 16 + q] = val;
        }
    }
}

// Final deterministic reduction of partials -> out[b][q]
__global__ __launch_bounds__(256)
void k_reduce(const float* __restrict__ part, float* __restrict__ out) {
    int idx = blockIdx.x * 256 + threadIdx.x;
    int b = idx >> 4, q = idx & 15;
    float s = 0.f;
    #pragma unroll
    for (int gp = 0; gp < 16; gp++) s += part[(b * 16 + gp) * 16 + q];
    out[idx] = s;
}

// ---------------------------------------------------------------------------
extern "C" void kernel_launch(void* const* d_in, const int* in_sizes, int n_in,
                              void* d_out, int out_size) {
    const float* x = (const float*)d_in[0];
    const float* w = (const float*)d_in[1];
    if (n_in >= 2 && in_sizes[0] == 192) { const float* t = x; x = w; w = t; }
    float* out = (float*)d_out;

    float4 *s0, *s1; float* part;
    cudaGetSymbolAddress((void**)&s0, g_state0);
    cudaGetSymbolAddress((void**)&s1, g_state1);
    cudaGetSymbolAddress((void**)&part, g_partial);

    k_tab<<<dim3(2, BATCH), 256>>>(x, w);
    k_matlow<<<dim3(32, BATCH), 256>>>(s0);            // materialize + L2 lo gates

    k_high<false><<<dim3(16, BATCH), 512>>>(2, (const float2*)s0, (float2*)s1, nullptr);

    k_low <<<dim3(32, BATCH), 256>>>(3, s1);
    k_high<true> <<<dim3(16, BATCH), 512>>>(3, (const float2*)s1, nullptr, part);

    k_reduce<<<8, 256>>>(part, out);
}

// round 17
// speedup vs baseline: 1.4740x; 1.0354x over previous
#include <cuda_runtime.h>
#include <cstdint>

#define N_QUBITS 16
#define DIM 65536
#define BATCH 128

// State buffer (single buffer now) + readout partials.
__device__ __align__(16) float4 g_state0[BATCH * DIM / 2];
__device__ float g_partial[BATCH * 16 * 16];   // [b][loGroup][q]

// Gate / table data.
__device__ float2 g_cs [BATCH * 4 * 16];               // ZYZ rotation (c,s); slot 3 used
__device__ __align__(16) float2 g_F4 [BATCH * 4 * 256];   // rank-4 lo tables (post-L1)
__device__ __align__(16) float2 g_G4 [BATCH * 4 * 256];   // rank-4 hi tables (post-L1)
__device__ __align__(16) float2 g_TL3[BATCH * 256];       // pure q0(L3) lo diagonal
__device__ __align__(16) float2 g_TH3[BATCH * 256];       // pure q0(L3) hi diagonal
// rank-16 post-L2 tables, sigma2-permuted & diagonal-folded:
//   g_Fp[((b*2+plane)*16+kp)*256 + jlo] = F16_kp[L(jlo,plane)] * TL3[jlo]
__device__ __align__(16) float2 g_Fp [BATCH * 2 * 16 * 256];
//   g_Gc[(b*256+hi)*32 + e*16 + kp]    = G16_kp[H(hi,e)] * TH3[hi]
__device__ __align__(16) float2 g_Gc [BATCH * 256 * 32];

// ---------------------------------------------------------------------------
__device__ __forceinline__ float2 cmul(float2 a, float2 b) {
    return make_float2(a.x * b.x - a.y * b.y, a.x * b.y + a.y * b.x);
}
__device__ __forceinline__ float2 sel(float2 v, int bit) {
    return bit ? make_float2(v.x, -v.y) : v;
}
__device__ __forceinline__ void rot2(float2& A, float2& B, float c, float s) {
    float2 a = A, b = B;
    A = make_float2(c * a.x - s * b.x, c * a.y - s * b.y);
    B = make_float2(s * a.x + c * b.x, s * a.y + c * b.y);
}

// ---------------------------------------------------------------------------
// First column of G = Rot(phi,theta,omega) @ RY(x): G00=(g0,g1), G10=(g4,g5).
__device__ void gate_col(const float* __restrict__ x,
                         const float* __restrict__ w,
                         int b, int l, int q,
                         float& g0, float& g1, float& g4, float& g5) {
    float xv  = x[(b * 4 + l) * 16 + q];
    const float* wp = w + (l * 16 + q) * 3;
    float phi = wp[0], th = wp[1], om = wp[2];
    float ct, st, cr, sr, sp, cp, sm, cm;
    sincosf(0.5f * th, &st, &ct);
    sincosf(0.5f * xv, &sr, &cr);
    sincosf(0.5f * (phi + om), &sp, &cp);
    sincosf(0.5f * (phi - om), &sm, &cm);
    float m00r =  cp * ct, m00i = -sp * ct;
    float m01r = -cm * st, m01i = -sm * st;
    float m10r =  cm * st, m10i = -sm * st;
    float m11r =  cp * ct, m11i =  sp * ct;
    g0 = m00r * cr + m01r * sr;  g1 = m00i * cr + m01i * sr;
    g4 = m10r * cr + m11r * sr;  g5 = m10i * cr + m11i * sr;
}

__device__ void gate_decomp(const float* __restrict__ x,
                            const float* __restrict__ w,
                            int b, int l, int q,
                            float2& cs, float2& q0, float2& p0) {
    float g0, g1, g4, g5;
    gate_col(x, w, b, l, q, g0, g1, g4, g5);
    float ca = sqrtf(g0 * g0 + g1 * g1);
    float sb = sqrtf(g4 * g4 + g5 * g5);
    float au = atan2f(g1, g0);
    float av = atan2f(g5, g4);
    float s1, c1, s2, c2;
    sincosf(0.5f * (au + av), &s1, &c1);
    sincosf(0.5f * (au - av), &s2, &c2);
    cs = make_float2(ca, sb);
    q0 = make_float2(c1, s1);
    p0 = make_float2(c2, s2);
}

// ---------------------------------------------------------------------------
// K_TAB4: rank-4 tables post-sigma0 + full L1 gates (proven R14/R15 code),
// written raw (i-indexed). Plus layer-3 ZYZ: rotation coeffs + pure diagonal
// products TL3/TH3 (no coupling: L2 is applied as FULL gates downstream).
__global__ __launch_bounds__(256)
void k_tab4(const float* __restrict__ x, const float* __restrict__ w) {
    int b = blockIdx.y, side = blockIdx.x, tid = threadIdx.x;
    __shared__ float2 colA[8][2];      // layer-0 first columns (this side's bits)
    __shared__ float2 gl1[8][2];       // layer-1 full gates
    __shared__ float2 q3[8];
    __shared__ float2 T[4][256];

    if (tid < 8) {
        int q0q = (side == 0) ? (15 - tid) : (7 - tid);
        float a0, a1, b0, b1;
        gate_col(x, w, b, 0, q0q, a0, a1, b0, b1);
        colA[tid][0] = make_float2(a0, a1);
        colA[tid][1] = make_float2(b0, b1);
        gate_col(x, w, b, 1, q0q, a0, a1, b0, b1);
        gl1[tid][0] = make_float2(a0, a1);
        gl1[tid][1] = make_float2(b0, b1);
    } else if (tid < 16) {
        int p = tid - 8;
        int q = (side == 0) ? (15 - p) : (7 - p);
        float2 cs, q0, p0;
        gate_decomp(x, w, b, 3, q, cs, q0, p0);
        g_cs[(b * 4 + 3) * 16 + (side == 0 ? p : 8 + p)] = cs;
        q3[p] = q0;
    }
    __syncthreads();

    // ---- K=4 indicator tables (sigma0 maps inside) — proven ----
    {
        int m = tid;
        float2 z = make_float2(0.f, 0.f);
        if (side == 0) {
            float2 acc = colA[0][(m ^ (m >> 1)) & 1];
            #pragma unroll
            for (int p = 1; p <= 6; p++)
                acc = cmul(acc, colA[p][((m >> p) ^ (m >> (p + 1))) & 1]);
            int m7 = (m >> 7) & 1;
            float2 AL0 = cmul(acc, colA[7][m7]);
            float2 AL1 = cmul(acc, colA[7][m7 ^ 1]);
            int a = m & 1;
            T[a * 2 + 0][m] = AL0;  T[a * 2 + 1][m] = AL1;
            T[(a ^ 1) * 2 + 0][m] = z;  T[(a ^ 1) * 2 + 1][m] = z;
        } else {
            float2 acc = colA[0][(m ^ (m >> 1)) & 1];
            #pragma unroll
            for (int p = 1; p <= 5; p++)
                acc = cmul(acc, colA[p][((m >> p) ^ (m >> (p + 1))) & 1]);
            int h6 = (m >> 6) & 1, h7 = (m >> 7) & 1;
            float2 AH0 = cmul(acc, cmul(colA[6][h6 ^ h7],     colA[7][h7]));
            float2 AH1 = cmul(acc, cmul(colA[6][h6 ^ 1 ^ h7], colA[7][1 ^ h7]));
            int b2 = m & 1;
            T[0 * 2 + b2][m] = AH0;  T[1 * 2 + b2][m] = AH1;
            T[0 * 2 + (b2 ^ 1)][m] = z;  T[1 * 2 + (b2 ^ 1)][m] = z;
        }
    }
    __syncthreads();

    // ---- full L1 gates on all 4 tables — proven ----
    #pragma unroll
    for (int p = 0; p < 8; p++) {
        float2 ga = gl1[p][0], gb = gl1[p][1];
        int mask = 1 << p;
        for (int it = tid; it < 512; it += 256) {
            int k = it >> 7, pi = it & 127;
            int low = pi & (mask - 1);
            int m0 = ((pi ^ low) << 1) | low;
            int m1 = m0 | mask;
            float2 t0 = T[k][m0], t1 = T[k][m1];
            T[k][m0] = make_float2(
                ga.x * t0.x - ga.y * t0.y - (gb.x * t1.x + gb.y * t1.y),
                ga.x * t0.y + ga.y * t0.x - (gb.x * t1.y - gb.y * t1.x));
            T[k][m1] = make_float2(
                gb.x * t0.x - gb.y * t0.y + (ga.x * t1.x + ga.y * t1.y),
                gb.x * t0.y + gb.y * t0.x + (ga.x * t1.y - ga.y * t1.x));
        }
        __syncthreads();
    }

    // ---- write raw tables + pure L3 diagonal products ----
    int m = tid;
    float2 d = sel(q3[0], m & 1);
    #pragma unroll
    for (int p = 1; p <= 7; p++) d = cmul(d, sel(q3[p], (m >> p) & 1));
    if (side == 0) {
        #pragma unroll
        for (int k = 0; k < 4; k++)
            g_F4[(b * 4 + k) * 256 + m] = T[k][m];
        g_TL3[b * 256 + m] = d;
    } else {
        #pragma unroll
        for (int k = 0; k < 4; k++)
            g_G4[(b * 4 + k) * 256 + m] = T[k][m];
        g_TH3[b * 256 + m] = d;
    }
}

// ---------------------------------------------------------------------------
// K_TAB16: sigma1-expand rank 4 -> 16 (proven index maps / indicator
// pairing: kp = k*4 + a*2 + b), apply FULL layer-2 gates table-wise, then
// write sigma2-pre-permuted, L3-diagonal-folded tables Fp / Gc.
__global__ __launch_bounds__(256)
void k_tab16(const float* __restrict__ x, const float* __restrict__ w) {
    int b = blockIdx.y, side = blockIdx.x, tid = threadIdx.x;
    __shared__ float2 gl2[8][2];
    __shared__ float2 F4s[4][256];
    __shared__ float2 T[16][256];
    __shared__ float2 D3[256];

    if (tid < 8) {
        int q = (side == 0) ? (15 - tid) : (7 - tid);
        float a0, a1, b0, b1;
        gate_col(x, w, b, 2, q, a0, a1, b0, b1);
        gl2[tid][0] = make_float2(a0, a1);
        gl2[tid][1] = make_float2(b0, b1);
    }
    {
        const float2* src = (side == 0) ? g_F4 : g_G4;
        for (int i = tid; i < 1024; i += 256)
            F4s[i >> 8][i & 255] = src[b * 1024 + i];
        D3[tid] = (side == 0) ? g_TL3[b * 256 + tid] : g_TH3[b * 256 + tid];
    }
    __syncthreads();

    // ---- sigma1 expansion ----
    {
        int m = tid;
        float2 z = make_float2(0.f, 0.f);
        int perm0 = (m ^ (m >> 1)) & 255;
        if (side == 0) {
            int a = m & 1;
            #pragma unroll
            for (int k = 0; k < 4; k++) {
                T[k * 4 + a * 2 + 0][m] = F4s[k][perm0];          // b=0 plane
                T[k * 4 + a * 2 + 1][m] = F4s[k][perm0 ^ 0x80];   // b=1 plane
                T[k * 4 + (a ^ 1) * 2 + 0][m] = z;
                T[k * 4 + (a ^ 1) * 2 + 1][m] = z;
            }
        } else {
            int bb = m & 1;
            #pragma unroll
            for (int k = 0; k < 4; k++) {
                T[k * 4 + 0 * 2 + bb][m] = F4s[k][perm0];          // a=0 plane
                T[k * 4 + 1 * 2 + bb][m] = F4s[k][perm0 ^ 0xC0];   // a=1 plane
                T[k * 4 + 0 * 2 + (bb ^ 1)][m] = z;
                T[k * 4 + 1 * 2 + (bb ^ 1)][m] = z;
            }
        }
    }
    __syncthreads();

    // ---- full L2 gates on all 16 tables ----
    #pragma unroll
    for (int p = 0; p < 8; p++) {
        float2 ga = gl2[p][0], gb = gl2[p][1];
        int mask = 1 << p;
        for (int it = tid; it < 2048; it += 256) {
            int kp = it >> 7, pi = it & 127;
            int low = pi & (mask - 1);
            int m0 = ((pi ^ low) << 1) | low;
            int m1 = m0 | mask;
            float2 t0 = T[kp][m0], t1 = T[kp][m1];
            T[kp][m0] = make_float2(
                ga.x * t0.x - ga.y * t0.y - (gb.x * t1.x + gb.y * t1.y),
                ga.x * t0.y + ga.y * t0.x - (gb.x * t1.y - gb.y * t1.x));
            T[kp][m1] = make_float2(
                gb.x * t0.x - gb.y * t0.y + (ga.x * t1.x + ga.y * t1.y),
                gb.x * t0.y + gb.y * t0.x + (ga.x * t1.y - ga.y * t1.x));
        }
        __syncthreads();
    }

    // ---- write sigma2-pre-permuted + diagonal-folded tables ----
    if (side == 0) {
        int jlo = tid;
        float2 d = D3[jlo];
        int l0 = (jlo ^ (jlo >> 1)) & 255;
        #pragma unroll
        for (int kp = 0; kp < 16; kp++) {
            g_Fp[((b * 2 + 0) * 16 + kp) * 256 + jlo] = cmul(T[kp][l0], d);
            g_Fp[((b * 2 + 1) * 16 + kp) * 256 + jlo] = cmul(T[kp][l0 ^ 0x80], d);
        }
    } else {
        int hi = tid;
        float2 d = D3[hi];
        int h0 = (hi ^ (hi >> 1)) & 255;
        #pragma unroll
        for (int kp = 0; kp < 16; kp++) {
            g_Gc[(b * 256 + hi) * 32 + kp]      = cmul(T[kp][h0], d);          // e=0
            g_Gc[(b * 256 + hi) * 32 + 16 + kp] = cmul(T[kp][h0 ^ 0xC0], d);   // e=1
        }
    }
}

// ---------------------------------------------------------------------------
// K_MAT16LOW: materialize the post-sigma2 state from the rank-16 tables
// (D2(L3) already folded) + fused layer-3 lo rotations (proven k_matlow body).
// grid (32, BATCH), 256 threads; warps of a block share hi PARITY so one
// Fp plane (32KB) serves the whole block. Conflict-free LDS.128 (4*lane%32).
__global__ __launch_bounds__(256)
void k_mat16low(float4* __restrict__ st4) {
    __shared__ __align__(16) float2 Fp_s[16 * 256];   // [kp][jlo], 32 KB
    __shared__ float2 cw[8][32];                       // [wid][e*16+kp]
    __shared__ float2 gcs[8];
    int b = blockIdx.y, blk = blockIdx.x, tid = threadIdx.x;
    int wid = tid >> 5, lane = tid & 31;
    int par = blk >> 4;
    int hi  = (((blk & 15) * 8 + wid) << 1) | par;

    if (tid < 8) gcs[tid] = g_cs[(b * 4 + 3) * 16 + tid];
    {
        const float4* src = (const float4*)(g_Fp + (size_t)(b * 2 + par) * 4096);
        float4* dst = (float4*)Fp_s;
        #pragma unroll
        for (int i = tid; i < 2048; i += 256) dst[i] = src[i];
    }
    cw[wid][lane] = g_Gc[(size_t)(b * 256 + hi) * 32 + lane];
    __syncthreads();

    // ---- rank-16 contraction: amp(jlo) = sum_kp Fp[kp][jlo] * c[jlo&1][kp] ----
    float4 v[4];
    #pragma unroll
    for (int r = 0; r < 4; r++) v[r] = make_float4(0.f, 0.f, 0.f, 0.f);
    const float4* F4v = (const float4*)Fp_s;
    #pragma unroll
    for (int kp = 0; kp < 16; kp++) {
        float2 c0 = cw[wid][kp];
        float2 c1 = cw[wid][16 + kp];
        #pragma unroll
        for (int r = 0; r < 4; r++) {
            float4 f = F4v[kp * 128 + r * 32 + lane];   // (jlo=2p, 2p+1)
            v[r].x += c0.x * f.x - c0.y * f.y;
            v[r].y += c0.x * f.y + c0.y * f.x;
            v[r].z += c1.x * f.z - c1.y * f.w;
            v[r].w += c1.x * f.w + c1.y * f.z;
        }
    }

    // ---- proven k_matlow gate body (layer-3 lo rotations) ----
    {
        float cc = gcs[0].x, ss = gcs[0].y;
        #pragma unroll
        for (int r = 0; r < 4; r++) {
            float4 a = v[r];
            v[r] = make_float4(cc * a.x - ss * a.z, cc * a.y - ss * a.w,
                               ss * a.x + cc * a.z, ss * a.y + cc * a.w);
        }
    }
    #pragma unroll
    for (int p = 1; p <= 5; p++) {
        float2 cp = gcs[p];
        float cc = cp.x;
        float ss = ((lane >> (p - 1)) & 1) ? cp.y : -cp.y;
        int msk = 1 << (p - 1);
        #pragma unroll
        for (int r = 0; r < 4; r++) {
            float px = __shfl_xor_sync(0xffffffffu, v[r].x, msk);
            float py = __shfl_xor_sync(0xffffffffu, v[r].y, msk);
            float pz = __shfl_xor_sync(0xffffffffu, v[r].z, msk);
            float pw = __shfl_xor_sync(0xffffffffu, v[r].w, msk);
            v[r].x = cc * v[r].x + ss * px;
            v[r].y = cc * v[r].y + ss * py;
            v[r].z = cc * v[r].z + ss * pz;
            v[r].w = cc * v[r].w + ss * pw;
        }
    }
    #pragma unroll
    for (int pb = 0; pb < 2; pb++) {
        int m = 1 << pb;
        float2 cp = gcs[6 + pb];
        float cc = cp.x, ss = cp.y;
        #pragma unroll
        for (int r = 0; r < 4; r++)
            if (!(r & m)) {
                float4 A = v[r], B = v[r + m];
                v[r]     = make_float4(cc * A.x - ss * B.x, cc * A.y - ss * B.y,
                                       cc * A.z - ss * B.z, cc * A.w - ss * B.w);
                v[r + m] = make_float4(ss * A.x + cc * B.x, ss * A.y + cc * B.y,
                                       ss * A.z + cc * B.z, ss * A.w + cc * B.w);
            }
    }
    float4* sbase = st4 + (size_t)b * (DIM / 2) + hi * 128;
    #pragma unroll
    for (int r = 0; r < 4; r++) sbase[r * 32 + lane] = v[r];
}

// ---------------------------------------------------------------------------
// K_FINAL: layer-3 hi rotations (zero-shuffle 3-phase) + signed-marginal
// readout. Proven R13-R15 FINAL path, standalone (no dTL/dTH).
__global__ __launch_bounds__(512)
void k_final(const float2* __restrict__ in, float* __restrict__ part) {
    __shared__ float2 tile[16 * 257];
    int b = blockIdx.y, logrp = blockIdx.x, tid = threadIdx.x;
    int base = b * 4 + 3;
    int lo4 = tid & 15, s = tid >> 4;
    float2 u[8];

    {
        const float2* gb = in + (size_t)b * DIM + (s << 3) * 256 + logrp * 16 + lo4;
        #pragma unroll
        for (int k = 0; k < 8; k++) u[k] = gb[k * 256];
        #pragma unroll
        for (int p = 0; p < 3; p++) {
            float2 cp = g_cs[base * 16 + 8 + p];
            int m = 1 << p;
            #pragma unroll
            for (int k = 0; k < 8; k++)
                if (!(k & m)) rot2(u[k], u[k + m], cp.x, cp.y);
        }
        #pragma unroll
        for (int k = 0; k < 8; k++)
            tile[lo4 * 257 + (s << 3) + k] = u[k];
    }
    __syncthreads();

    {
        int c = s & 7, d = s >> 3;
        int hbase = (d << 6) | c;
        #pragma unroll
        for (int m = 0; m < 8; m++) u[m] = tile[lo4 * 257 + hbase + (m << 3)];
        #pragma unroll
        for (int p = 0; p < 3; p++) {
            float2 cp = g_cs[base * 16 + 11 + p];
            int mm = 1 << p;
            #pragma unroll
            for (int m = 0; m < 8; m++)
                if (!(m & mm)) rot2(u[m], u[m + mm], cp.x, cp.y);
        }
        #pragma unroll
        for (int m = 0; m < 8; m++) tile[lo4 * 257 + hbase + (m << 3)] = u[m];
    }
    __syncthreads();

    {
        int hbase = s << 1;
        #pragma unroll
        for (int n = 0; n < 8; n++)
            u[n] = tile[lo4 * 257 + hbase + ((n >> 1) << 6) + (n & 1)];
        #pragma unroll
        for (int p = 0; p < 2; p++) {
            float2 cp = g_cs[base * 16 + 14 + p];
            int mm = 2 << p;
            #pragma unroll
            for (int n = 0; n < 8; n++)
                if (!(n & mm)) rot2(u[n], u[n + mm], cp.x, cp.y);
        }
    }

    __syncthreads();
    float* pf = (float*)tile;
    #pragma unroll
    for (int n = 0; n < 8; n++) {
        int hi = ((n >> 1) << 6) | (s << 1) | (n & 1);
        pf[lo4 * 257 + hi] = u[n].x * u[n].x + u[n].y * u[n].y;
    }
    __syncthreads();

    int wid = tid >> 5, lane = tid & 31;
    float spv[8], smv[8];
    if (tid < 256) {
        #pragma unroll
        for (int r = 0; r < 8; r++) {
            float p0 = pf[(wid * 2)     * 257 + r * 32 + lane];
            float p1 = pf[(wid * 2 + 1) * 257 + r * 32 + lane];
            spv[r] = p0 + p1; smv[r] = p0 - p1;
        }
    }
    __syncthreads();
    float* S  = pf;
    float* S2 = pf + 4096;
    if (tid < 256) {
        #pragma unroll
        for (int r = 0; r < 8; r++) {
            S[wid * 256 + r * 32 + lane]        = spv[r];
            S[2048 + wid * 256 + r * 32 + lane] = smv[r];
        }
    }
    __syncthreads();

    if (tid < 256) {
        float V0 = 0.f, V1 = 0.f, V2 = 0.f, V3 = 0.f, V4 = 0.f;
        #pragma unroll
        for (int w2 = 0; w2 < 8; w2++) {
            float sp = S[w2 * 256 + tid];
            float sm = S[2048 + w2 * 256 + tid];
            int pw  = __popc(w2) & 1;
            int pw2 = __popc(w2 >> 1) & 1;
            int pw3 = (w2 >> 2) & 1;
            V4 += sp;
            V1 += pw  ? -sp : sp;
            V2 += pw2 ? -sp : sp;
            V3 += pw3 ? -sp : sp;
            V0 += pw  ? -sm : sm;
        }
        float A[12];
        int t = tid;
        int pfb = __popc(t) & 1;
        #pragma unroll
        for (int k = 0; k < 7; k++)
            A[k] = (__popc(t >> k) & 1) ? -V4 : V4;
        A[7]  = pfb ? -V0 : V0;
        A[8]  = pfb ? -V1 : V1;
        A[9]  = pfb ? -V2 : V2;
        A[10] = pfb ? -V3 : V3;
        A[11] = (__popc(t & 0x7F) & 1) ? -V0 : V0;
        #pragma unroll
        for (int k = 0; k < 12; k++) {
            float a = A[k];
            #pragma unroll
            for (int o = 16; o; o >>= 1) a += __shfl_down_sync(0xffffffffu, a, o);
            if (lane == 0) S2[wid * 12 + k] = a;
        }
    }
    __syncthreads();
    if (tid < 12) {
        float sum = 0.f;
        #pragma unroll
        for (int w2 = 0; w2 < 8; w2++) sum += S2[w2 * 12 + tid];
        S2[96 + tid] = sum;
    }
    __syncthreads();
    if (tid < 16) {
        const float* R = S2 + 96;
        int q = tid, lg = logrp;
        float sgnAll = (__popc(lg) & 1) ? -1.f : 1.f;
        float val;
        if (q == 0)        val = sgnAll * R[11];
        else if (q < 8)    val = R[7 - q];
        else if (q < 12) {
            int P = 15 - q;
            val = ((__popc(lg >> (P - 4)) & 1) ? -1.f : 1.f) * R[0];
        } else {
            int P = 15 - q;
            val = sgnAll * R[7 + P];
        }
        part[(b * 16 + lg) * 16 + q] = val;
    }
}

// Final deterministic reduction of partials -> out[b][q]
__global__ __launch_bounds__(256)
void k_reduce(const float* __restrict__ part, float* __restrict__ out) {
    int idx = blockIdx.x * 256 + threadIdx.x;
    int b = idx >> 4, q = idx & 15;
    float s = 0.f;
    #pragma unroll
    for (int gp = 0; gp < 16; gp++) s += part[(b * 16 + gp) * 16 + q];
    out[idx] = s;
}

// ---------------------------------------------------------------------------
extern "C" void kernel_launch(void* const* d_in, const int* in_sizes, int n_in,
                              void* d_out, int out_size) {
    const float* x = (const float*)d_in[0];
    const float* w = (const float*)d_in[1];
    if (n_in >= 2 && in_sizes[0] == 192) { const float* t = x; x = w; w = t; }
    float* out = (float*)d_out;

    float4* s0; float* part;
    cudaGetSymbolAddress((void**)&s0, g_state0);
    cudaGetSymbolAddress((void**)&part, g_partial);

    k_tab4   <<<dim3(2, BATCH), 256>>>(x, w);
    k_tab16  <<<dim3(2, BATCH), 256>>>(x, w);
    k_mat16low<<<dim3(32, BATCH), 256>>>(s0);
    k_final  <<<dim3(16, BATCH), 512>>>((const float2*)s0, part);
    k_reduce <<<8, 256>>>(part, out);
}